// round 1
// baseline (speedup 1.0000x reference)
#include <cuda_runtime.h>

// Bilinear attention (no softmax) — fully linear, so reassociate:
//   out[b] = x[b] @ C[b],  C[b] = sum_h Wq[h] (Wk[h]^T G[b] Wv[h]) Wo[h],
//   G[b] = x[b]^T x[b]  (symmetric).
// Heavy work: G (2.15 GMAC) and x@C (2.15 GMAC). Middle chain ~0.6 GMAC.

#define LSEQ 4096
#define DIN  512
#define NH   8
#define NB   2

// Scratch (device globals — no allocation allowed)
__device__ float g_G[NB * 512 * 512];   // x^T x per batch
__device__ float g_P[NB * 512 * 512];   // P[b][n][h*64+k] = sum_m G[n][m] Wk[h][m][k]
__device__ float g_R[NB * NH * 64 * 64];// R[b,h][k][v]   = sum_n P[b][n][h*64+k] Wv[h][n][v]
__device__ float g_U[NB * 512 * 512];   // U[b][j][h*64+v]= sum_k Wq[h][j][k] R[b,h][k][v]
__device__ float g_C[NB * 512 * 512];   // C[b] = Ucat @ Wo_flat

// ---------------------------------------------------------------------------
// Shared tile loaders. Smem layout is always S[kk][0..63] (reduction-major).
// L1: source has reduction dim strided (ldk), 64-wide row contiguous.
// L2: source row-major with rows = output rows, reduction dim contiguous.
// ---------------------------------------------------------------------------
__device__ __forceinline__ void load_L1(float S[16][64], const float* __restrict__ src, int ldk) {
    int kk = threadIdx.x >> 4;          // 0..15
    int r4 = (threadIdx.x & 15) * 4;    // 0..60
    *reinterpret_cast<float4*>(&S[kk][r4]) =
        *reinterpret_cast<const float4*>(&src[kk * ldk + r4]);
}

__device__ __forceinline__ void load_L2(float S[16][64], const float* __restrict__ src, int lda) {
    int r  = threadIdx.x >> 2;          // 0..63
    int kg = (threadIdx.x & 3) * 4;     // 0,4,8,12
    float4 v = *reinterpret_cast<const float4*>(&src[r * lda + kg]);
    S[kg + 0][r] = v.x;
    S[kg + 1][r] = v.y;
    S[kg + 2][r] = v.z;
    S[kg + 3][r] = v.w;
}

__device__ __forceinline__ void mma16(float acc[4][4],
                                      const float A[16][64], const float B[16][64],
                                      int ty, int tx) {
#pragma unroll
    for (int kk = 0; kk < 16; kk++) {
        float4 a = *reinterpret_cast<const float4*>(&A[kk][ty * 4]);
        float4 b = *reinterpret_cast<const float4*>(&B[kk][tx * 4]);
        acc[0][0] += a.x * b.x; acc[0][1] += a.x * b.y; acc[0][2] += a.x * b.z; acc[0][3] += a.x * b.w;
        acc[1][0] += a.y * b.x; acc[1][1] += a.y * b.y; acc[1][2] += a.y * b.z; acc[1][3] += a.y * b.w;
        acc[2][0] += a.z * b.x; acc[2][1] += a.z * b.y; acc[2][2] += a.z * b.z; acc[2][3] += a.z * b.w;
        acc[3][0] += a.w * b.x; acc[3][1] += a.w * b.y; acc[3][2] += a.w * b.z; acc[3][3] += a.w * b.w;
    }
}

// ---------------------------------------------------------------------------
// K1: G[b] = x[b]^T x[b].  Symmetric: compute upper-triangular tile pairs,
// store tile + mirror. grid = (36, 1, B).
// ---------------------------------------------------------------------------
__global__ void k1_syrk(const float* __restrict__ x) {
    __shared__ __align__(16) float As[16][64];
    __shared__ __align__(16) float Bs[16][64];
    int b = blockIdx.z;
    int p = blockIdx.x;
    int ti = 0;
    while (p >= 8 - ti) { p -= 8 - ti; ti++; }
    int tj = ti + p;

    const float* xb = x + (size_t)b * LSEQ * DIN;
    int tx = threadIdx.x & 15, ty = threadIdx.x >> 4;
    float acc[4][4] = {};

    for (int k0 = 0; k0 < LSEQ; k0 += 16) {
        load_L1(As, xb + (size_t)k0 * DIN + ti * 64, DIN);
        load_L1(Bs, xb + (size_t)k0 * DIN + tj * 64, DIN);
        __syncthreads();
        mma16(acc, As, Bs, ty, tx);
        __syncthreads();
    }

    float* Gb = g_G + b * 512 * 512;
    int r0 = ti * 64 + ty * 4, c0 = tj * 64 + tx * 4;
#pragma unroll
    for (int i = 0; i < 4; i++)
        *reinterpret_cast<float4*>(&Gb[(r0 + i) * 512 + c0]) =
            make_float4(acc[i][0], acc[i][1], acc[i][2], acc[i][3]);
    if (ti != tj) {
#pragma unroll
        for (int i = 0; i < 4; i++)
#pragma unroll
            for (int j = 0; j < 4; j++)
                Gb[(c0 + j) * 512 + r0 + i] = acc[i][j];
    }
}

// ---------------------------------------------------------------------------
// K2: P[b][n][h*64+k] = sum_m G[b][n][m] Wk[h][m][k].  grid = (8, 8, B):
// x = head tile (h), y = n tile.
// ---------------------------------------------------------------------------
__global__ void k2_P(const float* __restrict__ Wk) {
    __shared__ __align__(16) float As[16][64];
    __shared__ __align__(16) float Bs[16][64];
    int b = blockIdx.z, h = blockIdx.x, nb = blockIdx.y;
    const float* Gb = g_G + b * 512 * 512;
    int tx = threadIdx.x & 15, ty = threadIdx.x >> 4;
    float acc[4][4] = {};

    for (int m0 = 0; m0 < 512; m0 += 16) {
        load_L2(As, Gb + nb * 64 * 512 + m0, 512);          // As[kk][n] = G[n][m0+kk]
        load_L1(Bs, Wk + h * 512 * 64 + m0 * 64, 64);       // Bs[kk][k] = Wk[h][m0+kk][k]
        __syncthreads();
        mma16(acc, As, Bs, ty, tx);
        __syncthreads();
    }

    float* Pb = g_P + b * 512 * 512;
    int r0 = nb * 64 + ty * 4, c0 = h * 64 + tx * 4;
#pragma unroll
    for (int i = 0; i < 4; i++)
        *reinterpret_cast<float4*>(&Pb[(r0 + i) * 512 + c0]) =
            make_float4(acc[i][0], acc[i][1], acc[i][2], acc[i][3]);
}

// ---------------------------------------------------------------------------
// K3: R[b,h][k][v] = sum_n P[b][n][h*64+k] Wv[h][n][v].  grid = (B*H).
// ---------------------------------------------------------------------------
__global__ void k3_R(const float* __restrict__ Wv) {
    __shared__ __align__(16) float As[16][64];
    __shared__ __align__(16) float Bs[16][64];
    int idx = blockIdx.x;               // b*8 + h
    int b = idx >> 3, h = idx & 7;
    const float* Pb = g_P + b * 512 * 512;
    int tx = threadIdx.x & 15, ty = threadIdx.x >> 4;
    float acc[4][4] = {};

    for (int m0 = 0; m0 < 512; m0 += 16) {
        load_L1(As, Pb + m0 * 512 + h * 64, 512);           // As[kk][k] = P[m0+kk][h*64+k]
        load_L1(Bs, Wv + h * 512 * 64 + m0 * 64, 64);       // Bs[kk][v] = Wv[h][m0+kk][v]
        __syncthreads();
        mma16(acc, As, Bs, ty, tx);
        __syncthreads();
    }

    float* Rd = g_R + idx * 64 * 64;
    int r0 = ty * 4, c0 = tx * 4;
#pragma unroll
    for (int i = 0; i < 4; i++)
        *reinterpret_cast<float4*>(&Rd[(r0 + i) * 64 + c0]) =
            make_float4(acc[i][0], acc[i][1], acc[i][2], acc[i][3]);
}

// ---------------------------------------------------------------------------
// K4: U[b][j][h*64+v] = sum_k Wq[h][j][k] R[b,h][k][v].  grid = (8, 8, B).
// ---------------------------------------------------------------------------
__global__ void k4_U(const float* __restrict__ Wq) {
    __shared__ __align__(16) float As[16][64];
    __shared__ __align__(16) float Bs[16][64];
    int b = blockIdx.z, h = blockIdx.x, jb = blockIdx.y;
    const float* Rd = g_R + (b * NH + h) * 64 * 64;
    int tx = threadIdx.x & 15, ty = threadIdx.x >> 4;
    float acc[4][4] = {};

    for (int t0 = 0; t0 < 64; t0 += 16) {
        load_L2(As, Wq + h * 512 * 64 + jb * 64 * 64 + t0, 64); // As[kk][j] = Wq[h][j][t0+kk]
        load_L1(Bs, Rd + t0 * 64, 64);                          // Bs[kk][v] = R[t0+kk][v]
        __syncthreads();
        mma16(acc, As, Bs, ty, tx);
        __syncthreads();
    }

    float* Ub = g_U + b * 512 * 512;
    int r0 = jb * 64 + ty * 4, c0 = h * 64 + tx * 4;
#pragma unroll
    for (int i = 0; i < 4; i++)
        *reinterpret_cast<float4*>(&Ub[(r0 + i) * 512 + c0]) =
            make_float4(acc[i][0], acc[i][1], acc[i][2], acc[i][3]);
}

// ---------------------------------------------------------------------------
// K5: C[b] = U[b] (512x512) @ Wo_flat (512x512).  grid = (8, 8, B).
// ---------------------------------------------------------------------------
__global__ void k5_C(const float* __restrict__ Wo) {
    __shared__ __align__(16) float As[16][64];
    __shared__ __align__(16) float Bs[16][64];
    int b = blockIdx.z, ob = blockIdx.x, jb = blockIdx.y;
    const float* Ub = g_U + b * 512 * 512;
    int tx = threadIdx.x & 15, ty = threadIdx.x >> 4;
    float acc[4][4] = {};

    for (int c0 = 0; c0 < 512; c0 += 16) {
        load_L2(As, Ub + jb * 64 * 512 + c0, 512);          // As[kk][j] = U[j][c0+kk]
        load_L1(Bs, Wo + c0 * 512 + ob * 64, 512);          // Bs[kk][o] = Wo_flat[c0+kk][o]
        __syncthreads();
        mma16(acc, As, Bs, ty, tx);
        __syncthreads();
    }

    float* Cb = g_C + b * 512 * 512;
    int r0 = jb * 64 + ty * 4, c0 = ob * 64 + tx * 4;
#pragma unroll
    for (int i = 0; i < 4; i++)
        *reinterpret_cast<float4*>(&Cb[(r0 + i) * 512 + c0]) =
            make_float4(acc[i][0], acc[i][1], acc[i][2], acc[i][3]);
}

// ---------------------------------------------------------------------------
// K6: out[b] = x[b] (4096x512) @ C[b] (512x512).  grid = (8, 64, B).
// ---------------------------------------------------------------------------
__global__ void k6_out(const float* __restrict__ x, float* __restrict__ out) {
    __shared__ __align__(16) float As[16][64];
    __shared__ __align__(16) float Bs[16][64];
    int b = blockIdx.z, ob = blockIdx.x, lb = blockIdx.y;
    const float* xb = x + (size_t)b * LSEQ * DIN;
    const float* Cb = g_C + b * 512 * 512;
    int tx = threadIdx.x & 15, ty = threadIdx.x >> 4;
    float acc[4][4] = {};

    for (int j0 = 0; j0 < 512; j0 += 16) {
        load_L2(As, xb + (size_t)lb * 64 * 512 + j0, 512);  // As[kk][l] = x[l][j0+kk]
        load_L1(Bs, Cb + j0 * 512 + ob * 64, 512);          // Bs[kk][o] = C[j0+kk][o]
        __syncthreads();
        mma16(acc, As, Bs, ty, tx);
        __syncthreads();
    }

    float* ob_ptr = out + (size_t)b * LSEQ * DIN;
    int r0 = lb * 64 + ty * 4, c0 = ob * 64 + tx * 4;
#pragma unroll
    for (int i = 0; i < 4; i++)
        *reinterpret_cast<float4*>(&ob_ptr[(size_t)(r0 + i) * DIN + c0]) =
            make_float4(acc[i][0], acc[i][1], acc[i][2], acc[i][3]);
}

// ---------------------------------------------------------------------------
extern "C" void kernel_launch(void* const* d_in, const int* in_sizes, int n_in,
                              void* d_out, int out_size) {
    const float* x  = (const float*)d_in[0];
    const float* Wq = (const float*)d_in[1];
    const float* Wk = (const float*)d_in[2];
    const float* Wv = (const float*)d_in[3];
    const float* Wo = (const float*)d_in[4];
    float* out = (float*)d_out;

    dim3 thr(256);
    k1_syrk<<<dim3(36, 1, NB), thr>>>(x);
    k2_P   <<<dim3(8, 8, NB), thr>>>(Wk);
    k3_R   <<<dim3(NB * NH),  thr>>>(Wv);
    k4_U   <<<dim3(8, 8, NB), thr>>>(Wq);
    k5_C   <<<dim3(8, 8, NB), thr>>>(Wo);
    k6_out <<<dim3(8, 64, NB), thr>>>(x, out);
}

// round 3
// speedup vs baseline: 1.9859x; 1.9859x over previous
#include <cuda_runtime.h>
#include <cuda_bf16.h>
#include <cstdint>

#define LSEQ 4096
#define DIN  512
#define NH   8
#define NB   2
#define GSPLIT 4

typedef unsigned short ushort_t;

// ---------------- device scratch (no allocation allowed) ----------------
__device__ ushort_t g_xh [NB * LSEQ * DIN];      // x bf16 hi, row-major
__device__ ushort_t g_xl [NB * LSEQ * DIN];
__device__ ushort_t g_xTh[NB * DIN * LSEQ];      // x^T bf16 hi  [b][d][l]
__device__ ushort_t g_xTl[NB * DIN * LSEQ];
__device__ float    g_Gp [NB * GSPLIT * 512 * 512];  // G split-K partials
__device__ ushort_t g_Gh [NB * 512 * 512];
__device__ ushort_t g_Gl [NB * 512 * 512];
__device__ float    g_P  [NB * 512 * 512];
__device__ float    g_R  [NB * NH * 64 * 64];
__device__ ushort_t g_Uh [NB * 512 * 512];
__device__ ushort_t g_Ul [NB * 512 * 512];
__device__ ushort_t g_CTh[NB * 512 * 512];       // C^T bf16  [o][j]
__device__ ushort_t g_CTl[NB * 512 * 512];
__device__ ushort_t g_Wkbh[512 * 512];           // Wk packed: [c=h*64+k][m]
__device__ ushort_t g_Wkbl[512 * 512];
__device__ ushort_t g_Wobh[512 * 512];           // Wo packed: [o][hv]
__device__ ushort_t g_Wobl[512 * 512];

// ---------------- helpers ----------------
#define SWZ(o) ((o) ^ (((o) >> 3) & 0x70))

__device__ __forceinline__ uint32_t smem_u32(const void* p) {
    uint32_t a;
    asm("{ .reg .u64 t; cvta.to.shared.u64 t, %1; cvt.u32.u64 %0, t; }" : "=r"(a) : "l"(p));
    return a;
}
__device__ __forceinline__ ushort_t f2bf(float v) {
    __nv_bfloat16 b = __float2bfloat16(v);
    return *reinterpret_cast<ushort_t*>(&b);
}
__device__ __forceinline__ float bfhi(ushort_t h) {
    return __uint_as_float(((uint32_t)h) << 16);
}

__device__ __forceinline__ void ldsm4(uint32_t* f, uint32_t addr) {
    asm volatile("ldmatrix.sync.aligned.m8n8.x4.shared.b16 {%0,%1,%2,%3}, [%4];"
                 : "=r"(f[0]), "=r"(f[1]), "=r"(f[2]), "=r"(f[3]) : "r"(addr));
}
__device__ __forceinline__ void mma16816(float* d, const uint32_t* a, const uint32_t* b) {
    asm volatile("mma.sync.aligned.m16n8k16.row.col.f32.bf16.bf16.f32 "
                 "{%0,%1,%2,%3}, {%4,%5,%6,%7}, {%8,%9}, {%0,%1,%2,%3};"
                 : "+f"(d[0]), "+f"(d[1]), "+f"(d[2]), "+f"(d[3])
                 : "r"(a[0]), "r"(a[1]), "r"(a[2]), "r"(a[3]), "r"(b[0]), "r"(b[1]));
}

// ---------------- generic bf16x3 GEMM ----------------
// C[M,N] = sum_k A(m,k)*B(n,k); A,B pre-split bf16 hi/lo, row-major with K
// contiguous (ld = lda/ldb). Tiles BM=BN=128, BK=32, 256 threads.
// EPI=0: fp32 row-major out. EPI=2: bf16 hi/lo TRANSPOSED out (out[c][r]).
struct Frag4 { uint4 h0, h1, l0, l1; };

__device__ __forceinline__ void load_bf(Frag4& f, const ushort_t* Hi, const ushort_t* Lo,
                                        int ld, int k0) {
    int r = threadIdx.x >> 1, kh = (threadIdx.x & 1) * 16;
    const ushort_t* ph = Hi + (size_t)r * ld + k0 + kh;
    const ushort_t* pl = Lo + (size_t)r * ld + k0 + kh;
    f.h0 = *(const uint4*)ph; f.h1 = *(const uint4*)(ph + 8);
    f.l0 = *(const uint4*)pl; f.l1 = *(const uint4*)(pl + 8);
}
__device__ __forceinline__ void store_bf(char* base, const Frag4& f) {
    int r = threadIdx.x >> 1, kh = (threadIdx.x & 1) * 16;
    uint32_t rowoff = (uint32_t)((r >> 1) * 128 + (r & 1) * 64 + kh * 2);
    uint32_t o0 = SWZ(rowoff), o1 = SWZ(rowoff + 16);
    *(uint4*)(base + o0) = f.h0;        *(uint4*)(base + o1) = f.h1;
    *(uint4*)(base + 8192 + o0) = f.l0; *(uint4*)(base + 8192 + o1) = f.l1;
}

static constexpr int STAGE_B = 32768;                 // Ah|Al|Bh|Bl  8KB each
static constexpr int GEMM_SMEM = 2 * STAGE_B;         // 65536

template <int EPI>
__global__ void __launch_bounds__(256, 1)
gemm_bf3(const ushort_t* __restrict__ Ah, const ushort_t* __restrict__ Al,
         const ushort_t* __restrict__ Bh, const ushort_t* __restrict__ Bl,
         float* __restrict__ Cf, ushort_t* __restrict__ Ch, ushort_t* __restrict__ Cl,
         int K, int lda, int ldb, int ldc,
         size_t bA, size_t bB, size_t bC, size_t slA, size_t slB, size_t slC, int nsl) {
    extern __shared__ char dsm[];
    uint32_t sb = smem_u32(dsm);
    int tid = threadIdx.x, lane = tid & 31, wid = tid >> 5;
    int wm = wid & 3, wn = wid >> 2;
    int z = blockIdx.z, b = z / nsl, sl = z - b * nsl;
    size_t offA = (size_t)b * bA + (size_t)sl * slA;
    size_t offB = (size_t)b * bB + (size_t)sl * slB;
    int m0 = blockIdx.y * 128, n0 = blockIdx.x * 128;
    const ushort_t* pAh = Ah + offA + (size_t)m0 * lda;
    const ushort_t* pAl = Al + offA + (size_t)m0 * lda;
    const ushort_t* pBh = Bh + offB + (size_t)n0 * ldb;
    const ushort_t* pBl = Bl + offB + (size_t)n0 * ldb;

    float acc[2][8][4];
#pragma unroll
    for (int i = 0; i < 2; i++)
#pragma unroll
        for (int j = 0; j < 8; j++)
#pragma unroll
            for (int q = 0; q < 4; q++) acc[i][j][q] = 0.f;

    Frag4 fa, fb;
    load_bf(fa, pAh, pAl, lda, 0);
    load_bf(fb, pBh, pBl, ldb, 0);

    const int nkt = K >> 5;
#pragma unroll 1
    for (int kt = 0; kt < nkt; kt++) {
        char* st = dsm + (kt & 1) * STAGE_B;
        store_bf(st, fa);
        store_bf(st + 16384, fb);
        __syncthreads();
        if (kt + 1 < nkt) {
            load_bf(fa, pAh, pAl, lda, (kt + 1) << 5);
            load_bf(fb, pBh, pBl, ldb, (kt + 1) << 5);
        }
        uint32_t stb = sb + (kt & 1) * STAGE_B;
#pragma unroll
        for (int ks = 0; ks < 2; ks++) {
            uint32_t ah[2][4], al[2][4], bh2[4][4], bl2[4][4];
            int ar = wm * 32 + (lane & 15);
            int akk = ks * 16 + (lane >> 4) * 8;
#pragma unroll
            for (int mt = 0; mt < 2; mt++) {
                int r = ar + mt * 16;
                uint32_t off = SWZ((uint32_t)((r >> 1) * 128 + (r & 1) * 64 + akk * 2));
                ldsm4(ah[mt], stb + off);
                ldsm4(al[mt], stb + 8192 + off);
            }
            int bn = wn * 64 + (lane & 7) + ((lane >> 4) & 1) * 8;
            int bkk = ks * 16 + ((lane >> 3) & 1) * 8;
#pragma unroll
            for (int p = 0; p < 4; p++) {
                int r = bn + p * 16;
                uint32_t off = SWZ((uint32_t)((r >> 1) * 128 + (r & 1) * 64 + bkk * 2));
                ldsm4(bh2[p], stb + 16384 + off);
                ldsm4(bl2[p], stb + 24576 + off);
            }
#pragma unroll
            for (int mt = 0; mt < 2; mt++)
#pragma unroll
                for (int nt = 0; nt < 8; nt++) {
                    const uint32_t* h = &bh2[nt >> 1][(nt & 1) * 2];
                    const uint32_t* l = &bl2[nt >> 1][(nt & 1) * 2];
                    mma16816(acc[mt][nt], ah[mt], h);
                    mma16816(acc[mt][nt], al[mt], h);
                    mma16816(acc[mt][nt], ah[mt], l);
                }
        }
    }

    size_t offC = (size_t)b * bC + (size_t)sl * slC;
    int r0 = m0 + wm * 32 + (lane >> 2);
    int c0 = n0 + wn * 64 + (lane & 3) * 2;
    if (EPI == 0) {
        float* Co = Cf + offC;
#pragma unroll
        for (int mt = 0; mt < 2; mt++)
#pragma unroll
            for (int nt = 0; nt < 8; nt++) {
                int r = r0 + mt * 16, c = c0 + nt * 8;
                *(float2*)&Co[(size_t)r * ldc + c] =
                    make_float2(acc[mt][nt][0], acc[mt][nt][1]);
                *(float2*)&Co[(size_t)(r + 8) * ldc + c] =
                    make_float2(acc[mt][nt][2], acc[mt][nt][3]);
            }
    } else {
        ushort_t* Hh = Ch + offC;
        ushort_t* Hl = Cl + offC;
#pragma unroll
        for (int mt = 0; mt < 2; mt++)
#pragma unroll
            for (int nt = 0; nt < 8; nt++) {
#pragma unroll
                for (int q = 0; q < 4; q++) {
                    int rr = r0 + mt * 16 + (q >> 1) * 8;
                    int cc = c0 + nt * 8 + (q & 1);
                    float v = acc[mt][nt][q];
                    ushort_t h = f2bf(v);
                    Hh[(size_t)cc * ldc + rr] = h;
                    Hl[(size_t)cc * ldc + rr] = f2bf(v - bfhi(h));
                }
            }
    }
}

// ---------------- one-time conversion / packing kernels ----------------
__global__ void conv_rm(const float* __restrict__ x) {
    size_t i = (size_t)blockIdx.x * 256 + threadIdx.x;   // over NB*LSEQ*DIN/4
    float4 v = ((const float4*)x)[i];
    ushort_t h0 = f2bf(v.x), h1 = f2bf(v.y), h2 = f2bf(v.z), h3 = f2bf(v.w);
    ((ushort4*)g_xh)[i] = make_ushort4(h0, h1, h2, h3);
    ((ushort4*)g_xl)[i] = make_ushort4(f2bf(v.x - bfhi(h0)), f2bf(v.y - bfhi(h1)),
                                       f2bf(v.z - bfhi(h2)), f2bf(v.w - bfhi(h3)));
}

__global__ void conv_tr(const float* __restrict__ x) {
    __shared__ float s[32][33];
    int b = blockIdx.z, r0 = blockIdx.x * 32, c0 = blockIdx.y * 32;
    int tx = threadIdx.x, ty = threadIdx.y;              // (32, 8)
    const float* xb = x + (size_t)b * LSEQ * DIN;
#pragma unroll
    for (int q = 0; q < 4; q++)
        s[ty + 8 * q][tx] = xb[(size_t)(r0 + ty + 8 * q) * DIN + c0 + tx];
    __syncthreads();
#pragma unroll
    for (int q = 0; q < 4; q++) {
        int c = ty + 8 * q;
        float v = s[tx][c];
        ushort_t h = f2bf(v);
        size_t o = ((size_t)b * DIN + c0 + c) * LSEQ + r0 + tx;
        g_xTh[o] = h;
        g_xTl[o] = f2bf(v - bfhi(h));
    }
}

__global__ void pack_wk(const float* __restrict__ Wk) {
    int i = blockIdx.x * 256 + threadIdx.x;              // 512*512
    int c = i >> 9, m = i & 511;
    int h = c >> 6, kd = c & 63;
    float v = Wk[h * 32768 + m * 64 + kd];
    ushort_t hh = f2bf(v);
    g_Wkbh[i] = hh;
    g_Wkbl[i] = f2bf(v - bfhi(hh));
}
__global__ void pack_wo(const float* __restrict__ Wo) {
    int i = blockIdx.x * 256 + threadIdx.x;              // [o][hv]
    int o = i >> 9, hv = i & 511;
    float v = Wo[hv * 512 + o];
    ushort_t hh = f2bf(v);
    g_Wobh[i] = hh;
    g_Wobl[i] = f2bf(v - bfhi(hh));
}

__global__ void reduce_G() {
    int i = blockIdx.x * 256 + threadIdx.x;              // over NB*65536 float4s
    int b = i >> 16, e = i & 65535;
    const float4* p = (const float4*)g_Gp;
    float4 s = p[(size_t)(b * GSPLIT + 0) * 65536 + e];
#pragma unroll
    for (int q = 1; q < GSPLIT; q++) {
        float4 t = p[(size_t)(b * GSPLIT + q) * 65536 + e];
        s.x += t.x; s.y += t.y; s.z += t.z; s.w += t.w;
    }
    ushort_t h0 = f2bf(s.x), h1 = f2bf(s.y), h2 = f2bf(s.z), h3 = f2bf(s.w);
    size_t o = (size_t)b * 262144 + (size_t)e * 4;
    *(ushort4*)&g_Gh[o] = make_ushort4(h0, h1, h2, h3);
    *(ushort4*)&g_Gl[o] = make_ushort4(f2bf(s.x - bfhi(h0)), f2bf(s.y - bfhi(h1)),
                                       f2bf(s.z - bfhi(h2)), f2bf(s.w - bfhi(h3)));
}

// ---------------- FFMA middle kernels (tiny) ----------------
__device__ __forceinline__ void load_L1(float S[16][64], const float* __restrict__ src, int ldk) {
    int kk = threadIdx.x >> 4;
    int r4 = (threadIdx.x & 15) * 4;
    *reinterpret_cast<float4*>(&S[kk][r4]) =
        *reinterpret_cast<const float4*>(&src[kk * ldk + r4]);
}
__device__ __forceinline__ void load_L2(float S[16][64], const float* __restrict__ src, int lda) {
    int r = threadIdx.x >> 2;
    int kg = (threadIdx.x & 3) * 4;
    float4 v = *reinterpret_cast<const float4*>(&src[r * lda + kg]);
    S[kg + 0][r] = v.x; S[kg + 1][r] = v.y; S[kg + 2][r] = v.z; S[kg + 3][r] = v.w;
}
__device__ __forceinline__ void mma16f(float acc[4][4],
                                       const float A[16][64], const float B[16][64],
                                       int ty, int tx) {
#pragma unroll
    for (int kk = 0; kk < 16; kk++) {
        float4 a = *reinterpret_cast<const float4*>(&A[kk][ty * 4]);
        float4 b = *reinterpret_cast<const float4*>(&B[kk][tx * 4]);
        acc[0][0] += a.x * b.x; acc[0][1] += a.x * b.y; acc[0][2] += a.x * b.z; acc[0][3] += a.x * b.w;
        acc[1][0] += a.y * b.x; acc[1][1] += a.y * b.y; acc[1][2] += a.y * b.z; acc[1][3] += a.y * b.w;
        acc[2][0] += a.z * b.x; acc[2][1] += a.z * b.y; acc[2][2] += a.z * b.z; acc[2][3] += a.z * b.w;
        acc[3][0] += a.w * b.x; acc[3][1] += a.w * b.y; acc[3][2] += a.w * b.z; acc[3][3] += a.w * b.w;
    }
}

// K3: R[b,h][k][v] = sum_n P[b][n][h*64+k] Wv[h][n][v]
__global__ void k3_R(const float* __restrict__ Wv) {
    __shared__ __align__(16) float As[16][64];
    __shared__ __align__(16) float Bs[16][64];
    int idx = blockIdx.x, b = idx >> 3, h = idx & 7;
    const float* Pb = g_P + b * 512 * 512;
    int tx = threadIdx.x & 15, ty = threadIdx.x >> 4;
    float acc[4][4] = {};
    for (int m0 = 0; m0 < 512; m0 += 16) {
        load_L1(As, Pb + m0 * 512 + h * 64, 512);
        load_L1(Bs, Wv + h * 512 * 64 + m0 * 64, 64);
        __syncthreads();
        mma16f(acc, As, Bs, ty, tx);
        __syncthreads();
    }
    float* Rd = g_R + idx * 64 * 64;
    int r0 = ty * 4, c0 = tx * 4;
#pragma unroll
    for (int i = 0; i < 4; i++)
        *reinterpret_cast<float4*>(&Rd[(r0 + i) * 64 + c0]) =
            make_float4(acc[i][0], acc[i][1], acc[i][2], acc[i][3]);
}

// K4: U[b][j][h*64+v] = sum_k Wq[h][j][k] R[b,h][k][v]  -> bf16 hi/lo
__global__ void k4_U(const float* __restrict__ Wq) {
    __shared__ __align__(16) float As[16][64];
    __shared__ __align__(16) float Bs[16][64];
    int b = blockIdx.z, h = blockIdx.x, jb = blockIdx.y;
    const float* Rd = g_R + (b * NH + h) * 64 * 64;
    int tx = threadIdx.x & 15, ty = threadIdx.x >> 4;
    float acc[4][4] = {};
    for (int t0 = 0; t0 < 64; t0 += 16) {
        load_L2(As, Wq + h * 512 * 64 + jb * 64 * 64 + t0, 64);
        load_L1(Bs, Rd + t0 * 64, 64);
        __syncthreads();
        mma16f(acc, As, Bs, ty, tx);
        __syncthreads();
    }
    size_t base = (size_t)b * 262144;
    int r0 = jb * 64 + ty * 4, c0 = h * 64 + tx * 4;
#pragma unroll
    for (int i = 0; i < 4; i++) {
        ushort_t h0 = f2bf(acc[i][0]), h1 = f2bf(acc[i][1]);
        ushort_t h2 = f2bf(acc[i][2]), h3 = f2bf(acc[i][3]);
        size_t o = base + (size_t)(r0 + i) * 512 + c0;
        *(ushort4*)&g_Uh[o] = make_ushort4(h0, h1, h2, h3);
        *(ushort4*)&g_Ul[o] = make_ushort4(
            f2bf(acc[i][0] - bfhi(h0)), f2bf(acc[i][1] - bfhi(h1)),
            f2bf(acc[i][2] - bfhi(h2)), f2bf(acc[i][3] - bfhi(h3)));
    }
}

// ---------------------------------------------------------------------------
extern "C" void kernel_launch(void* const* d_in, const int* in_sizes, int n_in,
                              void* d_out, int out_size) {
    const float* x  = (const float*)d_in[0];
    const float* Wq = (const float*)d_in[1];
    const float* Wk = (const float*)d_in[2];
    const float* Wv = (const float*)d_in[3];
    const float* Wo = (const float*)d_in[4];
    float* out = (float*)d_out;

    cudaFuncSetAttribute(gemm_bf3<0>, cudaFuncAttributeMaxDynamicSharedMemorySize, GEMM_SMEM);
    cudaFuncSetAttribute(gemm_bf3<2>, cudaFuncAttributeMaxDynamicSharedMemorySize, GEMM_SMEM);

    ushort_t *xh, *xl, *xTh, *xTl, *Gh, *Gl, *Uh, *Ul, *CTh, *CTl, *Wkbh, *Wkbl, *Wobh, *Wobl;
    float *Gp, *P;
    cudaGetSymbolAddress((void**)&xh,  g_xh);  cudaGetSymbolAddress((void**)&xl,  g_xl);
    cudaGetSymbolAddress((void**)&xTh, g_xTh); cudaGetSymbolAddress((void**)&xTl, g_xTl);
    cudaGetSymbolAddress((void**)&Gh,  g_Gh);  cudaGetSymbolAddress((void**)&Gl,  g_Gl);
    cudaGetSymbolAddress((void**)&Uh,  g_Uh);  cudaGetSymbolAddress((void**)&Ul,  g_Ul);
    cudaGetSymbolAddress((void**)&CTh, g_CTh); cudaGetSymbolAddress((void**)&CTl, g_CTl);
    cudaGetSymbolAddress((void**)&Wkbh, g_Wkbh); cudaGetSymbolAddress((void**)&Wkbl, g_Wkbl);
    cudaGetSymbolAddress((void**)&Wobh, g_Wobh); cudaGetSymbolAddress((void**)&Wobl, g_Wobl);
    cudaGetSymbolAddress((void**)&Gp,  g_Gp);  cudaGetSymbolAddress((void**)&P,   g_P);

    const size_t bS  = 512 * 512;
    const size_t bX  = (size_t)LSEQ * DIN;

    conv_rm<<<(NB * LSEQ * DIN / 4) / 256, 256>>>(x);
    conv_tr<<<dim3(LSEQ / 32, DIN / 32, NB), dim3(32, 8)>>>(x);
    pack_wk<<<1024, 256>>>(Wk);
    pack_wo<<<1024, 256>>>(Wo);

    // G partials: A = B = x^T (KM, ld=LSEQ), split-K x4, K=1024 per slice
    gemm_bf3<0><<<dim3(4, 4, NB * GSPLIT), 256, GEMM_SMEM>>>(
        xTh, xTl, xTh, xTl, Gp, nullptr, nullptr,
        1024, LSEQ, LSEQ, 512,
        (size_t)DIN * LSEQ, (size_t)DIN * LSEQ, (size_t)GSPLIT * bS,
        1024, 1024, bS, GSPLIT);
    reduce_G<<<NB * 65536 / 256, 256>>>();

    // P = G @ Wk_packed  (fp32 out for FFMA consumer)
    gemm_bf3<0><<<dim3(4, 4, NB), 256, GEMM_SMEM>>>(
        Gh, Gl, Wkbh, Wkbl, P, nullptr, nullptr,
        512, 512, 512, 512, bS, 0, bS, 0, 0, 0, 1);

    k3_R<<<dim3(NB * NH), 256>>>(Wv);
    k4_U<<<dim3(8, 8, NB), 256>>>(Wq);

    // C^T (bf16 hi/lo) = (U @ Wo_packed)^T
    gemm_bf3<2><<<dim3(4, 4, NB), 256, GEMM_SMEM>>>(
        Uh, Ul, Wobh, Wobl, nullptr, CTh, CTl,
        512, 512, 512, 512, bS, 0, bS, 0, 0, 0, 1);

    // out = x @ C : A = x (KM bf16), B = C^T rows (o-major, j contiguous)
    gemm_bf3<0><<<dim3(4, 32, NB), 256, GEMM_SMEM>>>(
        xh, xl, CTh, CTl, out, nullptr, nullptr,
        512, 512, 512, 512, bX, bS, bX, 0, 0, 0, 1);
}

// round 4
// speedup vs baseline: 2.7754x; 1.3975x over previous
#include <cuda_runtime.h>
#include <cuda_bf16.h>
#include <cstdint>

#define LSEQ 4096
#define DIN  512
#define NH   8
#define NB   2

typedef unsigned short ushort_t;
static const size_t bS = 512 * 512;
static const size_t bX = (size_t)LSEQ * DIN;

// ---------------- device scratch ----------------
__device__ __align__(256) ushort_t g_xh [NB * LSEQ * DIN];
__device__ __align__(256) ushort_t g_xl [NB * LSEQ * DIN];
__device__ __align__(256) ushort_t g_xTh[NB * DIN * LSEQ];
__device__ __align__(256) ushort_t g_xTl[NB * DIN * LSEQ];
__device__ __align__(256) float    g_Gp [NB * 8 * 512 * 512];
__device__ __align__(256) ushort_t g_Gh [NB * 512 * 512];
__device__ __align__(256) ushort_t g_Gl [NB * 512 * 512];
__device__ __align__(256) float    g_Pp [NB * 4 * 512 * 512];
__device__ __align__(256) ushort_t g_PTh[NB * 512 * 512];
__device__ __align__(256) ushort_t g_PTl[NB * 512 * 512];
__device__ __align__(256) ushort_t g_RTh[NB * NH * 64 * 64];
__device__ __align__(256) ushort_t g_RTl[NB * NH * 64 * 64];
__device__ __align__(256) ushort_t g_Uh [NB * 512 * 512];
__device__ __align__(256) ushort_t g_Ul [NB * 512 * 512];
__device__ __align__(256) float    g_Cp [NB * 4 * 512 * 512];
__device__ __align__(256) ushort_t g_CTh[NB * 512 * 512];
__device__ __align__(256) ushort_t g_CTl[NB * 512 * 512];
__device__ __align__(256) ushort_t g_Wkbh[512 * 512];   // [c=h*64+k][m]
__device__ __align__(256) ushort_t g_Wkbl[512 * 512];
__device__ __align__(256) ushort_t g_Wobh[512 * 512];   // [o][hv]
__device__ __align__(256) ushort_t g_Wobl[512 * 512];
__device__ __align__(256) ushort_t g_WvTh[512 * 512];   // [hv][n]
__device__ __align__(256) ushort_t g_WvTl[512 * 512];
__device__ __align__(256) ushort_t g_Wqbh[512 * 64 * NH]; // [h*512+j][k]
__device__ __align__(256) ushort_t g_Wqbl[512 * 64 * NH];

// ---------------- helpers ----------------
#define SWZ(o) ((o) ^ (((o) >> 3) & 0x70))

__device__ __forceinline__ uint32_t smem_u32(const void* p) {
    uint32_t a;
    asm("{ .reg .u64 t; cvta.to.shared.u64 t, %1; cvt.u32.u64 %0, t; }" : "=r"(a) : "l"(p));
    return a;
}
__device__ __forceinline__ ushort_t f2bf(float v) {
    __nv_bfloat16 b = __float2bfloat16(v);
    return *reinterpret_cast<ushort_t*>(&b);
}
__device__ __forceinline__ float bfhi(ushort_t h) {
    return __uint_as_float(((uint32_t)h) << 16);
}
__device__ __forceinline__ void ldsm4(uint32_t* f, uint32_t addr) {
    asm volatile("ldmatrix.sync.aligned.m8n8.x4.shared.b16 {%0,%1,%2,%3}, [%4];"
                 : "=r"(f[0]), "=r"(f[1]), "=r"(f[2]), "=r"(f[3]) : "r"(addr));
}
__device__ __forceinline__ void mma16816(float* d, const uint32_t* a, const uint32_t* b) {
    asm volatile("mma.sync.aligned.m16n8k16.row.col.f32.bf16.bf16.f32 "
                 "{%0,%1,%2,%3}, {%4,%5,%6,%7}, {%8,%9}, {%0,%1,%2,%3};"
                 : "+f"(d[0]), "+f"(d[1]), "+f"(d[2]), "+f"(d[3])
                 : "r"(a[0]), "r"(a[1]), "r"(a[2]), "r"(a[3]), "r"(b[0]), "r"(b[1]));
}
__device__ __forceinline__ void cpa16(uint32_t s, const void* g) {
    asm volatile("cp.async.cg.shared.global [%0], [%1], 16;" :: "r"(s), "l"(g) : "memory");
}
#define CP_COMMIT() asm volatile("cp.async.commit_group;" ::: "memory")
#define CP_WAIT(n)  asm volatile("cp.async.wait_group %0;" :: "n"(n) : "memory")

// ===========================================================================
// Generic bf16x3 GEMM via mma.sync (HMMA): C(m,n) = sum_k A(m,k)*B(n,k).
// A, B pre-split bf16 hi/lo, K contiguous. 256 threads, warp grid 2(m)x4(n).
// EPI 0: fp32 row-major out. EPI 1: bf16 hi/lo row-major out.
// z = b*nsl + sl: offsets off{A,B,C} = b*b{A,B,C} + sl*sl{A,B,C}.
// ===========================================================================
template <int BM, int BN, int EPI>
__global__ void __launch_bounds__(256, 1)
gemm_bf3(const ushort_t* __restrict__ Ah, const ushort_t* __restrict__ Al,
         const ushort_t* __restrict__ Bh, const ushort_t* __restrict__ Bl,
         float* __restrict__ Cf, ushort_t* __restrict__ Ch, ushort_t* __restrict__ Cl,
         int K, int lda, int ldb, int ldc,
         long bA, long slA, long bB, long slB, long bC, long slC, int nsl) {
    constexpr int WM = BM / 2, WN = BN / 4;
    constexpr int MT = WM / 16, NT = WN / 8, PB = WN / 16;
    constexpr int SS = (BM + BN) * 128;          // stage bytes: Ah|Al|Bh|Bl

    extern __shared__ char dsm[];
    uint32_t sb = smem_u32(dsm);
    int tid = threadIdx.x, lane = tid & 31, wid = tid >> 5;
    int wm = wid & 1, wn = wid >> 1;

    int z = blockIdx.z, b = z / nsl, sl = z - b * nsl;
    int m0 = blockIdx.y * BM, n0 = blockIdx.x * BN;
    const ushort_t* pAh = Ah + b * bA + sl * slA + (size_t)m0 * lda;
    const ushort_t* pAl = Al + b * bA + sl * slA + (size_t)m0 * lda;
    const ushort_t* pBh = Bh + b * bB + sl * slB + (size_t)n0 * ldb;
    const ushort_t* pBl = Bl + b * bB + sl * slB + (size_t)n0 * ldb;

    float acc[MT][NT][4];
#pragma unroll
    for (int i = 0; i < MT; i++)
#pragma unroll
        for (int j = 0; j < NT; j++)
#pragma unroll
            for (int q = 0; q < 4; q++) acc[i][j][q] = 0.f;

    auto load_stage = [&](int st, int kt) {
        uint32_t s0 = sb + st * SS;
        int ke = kt * 32;
#pragma unroll
        for (int c = tid; c < BM * 4; c += 256) {
            int r = c >> 2, sg = c & 3;
            uint32_t o = SWZ((uint32_t)((r >> 1) * 128 + (r & 1) * 64 + sg * 16));
            cpa16(s0 + o,           pAh + (size_t)r * lda + ke + sg * 8);
            cpa16(s0 + BM * 64 + o, pAl + (size_t)r * lda + ke + sg * 8);
        }
#pragma unroll
        for (int c = tid; c < BN * 4; c += 256) {
            int r = c >> 2, sg = c & 3;
            uint32_t o = SWZ((uint32_t)((r >> 1) * 128 + (r & 1) * 64 + sg * 16));
            cpa16(s0 + BM * 128 + o,           pBh + (size_t)r * ldb + ke + sg * 8);
            cpa16(s0 + BM * 128 + BN * 64 + o, pBl + (size_t)r * ldb + ke + sg * 8);
        }
        CP_COMMIT();
    };

    const int nkt = K >> 5;
    load_stage(0, 0);

#pragma unroll 1
    for (int kt = 0; kt < nkt; kt++) {
        if (kt + 1 < nkt) { load_stage((kt + 1) & 1, kt + 1); CP_WAIT(1); }
        else              { CP_WAIT(0); }
        __syncthreads();

        uint32_t stb = sb + (kt & 1) * SS;
#pragma unroll
        for (int ks = 0; ks < 2; ks++) {
            uint32_t ah[MT][4], al[MT][4], bh[PB][4], bl[PB][4];
            int ar  = wm * WM + (lane & 15);
            int akk = ks * 16 + (lane >> 4) * 8;
#pragma unroll
            for (int mt = 0; mt < MT; mt++) {
                int r = ar + mt * 16;
                uint32_t o = SWZ((uint32_t)((r >> 1) * 128 + (r & 1) * 64 + akk * 2));
                ldsm4(ah[mt], stb + o);
                ldsm4(al[mt], stb + BM * 64 + o);
            }
            int bn  = wn * WN + (lane & 7) + ((lane >> 4) & 1) * 8;
            int bkk = ks * 16 + ((lane >> 3) & 1) * 8;
#pragma unroll
            for (int p = 0; p < PB; p++) {
                int r = bn + p * 16;
                uint32_t o = SWZ((uint32_t)((r >> 1) * 128 + (r & 1) * 64 + bkk * 2));
                ldsm4(bh[p], stb + BM * 128 + o);
                ldsm4(bl[p], stb + BM * 128 + BN * 64 + o);
            }
#pragma unroll
            for (int mt = 0; mt < MT; mt++)
#pragma unroll
                for (int nt = 0; nt < NT; nt++) {
                    const uint32_t* fh = &bh[nt >> 1][(nt & 1) * 2];
                    const uint32_t* fl = &bl[nt >> 1][(nt & 1) * 2];
                    mma16816(acc[mt][nt], ah[mt], fh);
                    mma16816(acc[mt][nt], al[mt], fh);
                    mma16816(acc[mt][nt], ah[mt], fl);
                }
        }
        __syncthreads();
    }

    long offC = b * bC + sl * slC;
    int r0 = m0 + wm * WM + (lane >> 2);
    int c0 = n0 + wn * WN + (lane & 3) * 2;
    if (EPI == 0) {
        float* Co = Cf + offC;
#pragma unroll
        for (int mt = 0; mt < MT; mt++)
#pragma unroll
            for (int nt = 0; nt < NT; nt++) {
                int r = r0 + mt * 16, c = c0 + nt * 8;
                *(float2*)&Co[(size_t)r * ldc + c] =
                    make_float2(acc[mt][nt][0], acc[mt][nt][1]);
                *(float2*)&Co[(size_t)(r + 8) * ldc + c] =
                    make_float2(acc[mt][nt][2], acc[mt][nt][3]);
            }
    } else {
        ushort_t* Hh = Ch + offC;
        ushort_t* Hl = Cl + offC;
#pragma unroll
        for (int mt = 0; mt < MT; mt++)
#pragma unroll
            for (int nt = 0; nt < NT; nt++)
#pragma unroll
                for (int hf = 0; hf < 2; hf++) {
                    int r = r0 + mt * 16 + hf * 8, c = c0 + nt * 8;
                    float v0 = acc[mt][nt][hf * 2], v1 = acc[mt][nt][hf * 2 + 1];
                    ushort_t h0 = f2bf(v0), h1 = f2bf(v1);
                    *(ushort2*)&Hh[(size_t)r * ldc + c] = make_ushort2(h0, h1);
                    *(ushort2*)&Hl[(size_t)r * ldc + c] =
                        make_ushort2(f2bf(v0 - bfhi(h0)), f2bf(v1 - bfhi(h1)));
                }
    }
}

// ===========================================================================
// Fused input pack: x hi/lo (row-major + transposed), Wk->[c][m], Wo->[o][hv],
// Wv->[hv][n], Wq->[h*512+j][k]; all bf16 hi/lo.
// ===========================================================================
__global__ void pack_all(const float* __restrict__ x, const float* __restrict__ Wq,
                         const float* __restrict__ Wk, const float* __restrict__ Wv,
                         const float* __restrict__ Wo) {
    __shared__ float s[32][33];
    int blk = blockIdx.x, tid = threadIdx.x;
    if (blk < 4096) {                      // x row-major split (float4 per thread)
        size_t i = (size_t)blk * 256 + tid;
        float4 v = ((const float4*)x)[i];
        ushort_t h0 = f2bf(v.x), h1 = f2bf(v.y), h2 = f2bf(v.z), h3 = f2bf(v.w);
        ((ushort4*)g_xh)[i] = make_ushort4(h0, h1, h2, h3);
        ((ushort4*)g_xl)[i] = make_ushort4(f2bf(v.x - bfhi(h0)), f2bf(v.y - bfhi(h1)),
                                           f2bf(v.z - bfhi(h2)), f2bf(v.w - bfhi(h3)));
    } else if (blk < 8192) {               // x transpose -> xT[d][l]
        int id = blk - 4096;
        int bx = id & 127, by = (id >> 7) & 15, b = id >> 11;
        int r0 = bx * 32, c0 = by * 32;
        int tx = tid & 31, ty = tid >> 5;
        const float* xb = x + (size_t)b * bX;
#pragma unroll
        for (int q = 0; q < 4; q++)
            s[ty + 8 * q][tx] = xb[(size_t)(r0 + ty + 8 * q) * DIN + c0 + tx];
        __syncthreads();
#pragma unroll
        for (int q = 0; q < 4; q++) {
            int cd = ty + 8 * q;
            float v = s[tx][cd];
            ushort_t h = f2bf(v);
            size_t o = ((size_t)b * DIN + c0 + cd) * LSEQ + r0 + tx;
            g_xTh[o] = h;
            g_xTl[o] = f2bf(v - bfhi(h));
        }
    } else if (blk < 9216) {               // Wkb[c][m] = Wk[h][m][k]
        int i = (blk - 8192) * 256 + tid;
        int c = i >> 9, m = i & 511, h = c >> 6, kd = c & 63;
        float v = Wk[h * 32768 + m * 64 + kd];
        ushort_t hh = f2bf(v);
        g_Wkbh[i] = hh; g_Wkbl[i] = f2bf(v - bfhi(hh));
    } else if (blk < 10240) {              // Wob[o][hv] = Wo[hv][o]
        int i = (blk - 9216) * 256 + tid;
        int o = i >> 9, hv = i & 511;
        float v = Wo[hv * 512 + o];
        ushort_t hh = f2bf(v);
        g_Wobh[i] = hh; g_Wobl[i] = f2bf(v - bfhi(hh));
    } else if (blk < 11264) {              // WvT[hv][n] = Wv[h][n][v]
        int i = (blk - 10240) * 256 + tid;
        int row = i >> 9, n = i & 511, h = row >> 6, vv = row & 63;
        float v = Wv[h * 32768 + n * 64 + vv];
        ushort_t hh = f2bf(v);
        g_WvTh[i] = hh; g_WvTl[i] = f2bf(v - bfhi(hh));
    } else {                               // Wqb straight split
        int i = (blk - 11264) * 256 + tid;
        float v = Wq[i];
        ushort_t hh = f2bf(v);
        g_Wqbh[i] = hh; g_Wqbl[i] = f2bf(v - bfhi(hh));
    }
}

// ===========================================================================
// Split-K reduce: sum NS fp32 partials per batch, emit bf16 hi/lo.
// ===========================================================================
template <int NS>
__global__ void reduce_ns(const float* __restrict__ src,
                          ushort_t* __restrict__ oh, ushort_t* __restrict__ ol) {
    int i = blockIdx.x * 256 + threadIdx.x;          // over NB*65536 float4
    int b = i >> 16, e = i & 65535;
    const float4* p = (const float4*)src;
    float4 v = p[(size_t)(b * NS) * 65536 + e];
#pragma unroll
    for (int q = 1; q < NS; q++) {
        float4 t = p[(size_t)(b * NS + q) * 65536 + e];
        v.x += t.x; v.y += t.y; v.z += t.z; v.w += t.w;
    }
    ushort_t h0 = f2bf(v.x), h1 = f2bf(v.y), h2 = f2bf(v.z), h3 = f2bf(v.w);
    size_t o = (size_t)b * 65536 + e;
    ((ushort4*)oh)[o] = make_ushort4(h0, h1, h2, h3);
    ((ushort4*)ol)[o] = make_ushort4(f2bf(v.x - bfhi(h0)), f2bf(v.y - bfhi(h1)),
                                     f2bf(v.z - bfhi(h2)), f2bf(v.w - bfhi(h3)));
}

// ===========================================================================
extern "C" void kernel_launch(void* const* d_in, const int* in_sizes, int n_in,
                              void* d_out, int out_size) {
    const float* x  = (const float*)d_in[0];
    const float* Wq = (const float*)d_in[1];
    const float* Wk = (const float*)d_in[2];
    const float* Wv = (const float*)d_in[3];
    const float* Wo = (const float*)d_in[4];
    float* out = (float*)d_out;

    cudaFuncSetAttribute(gemm_bf3<128,128,0>, cudaFuncAttributeMaxDynamicSharedMemorySize, 65536);
    cudaFuncSetAttribute(gemm_bf3<64,64,1>,   cudaFuncAttributeMaxDynamicSharedMemorySize, 32768);
    cudaFuncSetAttribute(gemm_bf3<128,64,1>,  cudaFuncAttributeMaxDynamicSharedMemorySize, 49152);

    ushort_t *xh,*xl,*xTh,*xTl,*Gh,*Gl,*PTh,*PTl,*RTh,*RTl,*Uh,*Ul,*CTh,*CTl;
    ushort_t *Wkbh,*Wkbl,*Wobh,*Wobl,*WvTh,*WvTl,*Wqbh,*Wqbl;
    float *Gp,*Pp,*Cp;
    cudaGetSymbolAddress((void**)&xh,  g_xh);  cudaGetSymbolAddress((void**)&xl,  g_xl);
    cudaGetSymbolAddress((void**)&xTh, g_xTh); cudaGetSymbolAddress((void**)&xTl, g_xTl);
    cudaGetSymbolAddress((void**)&Gh,  g_Gh);  cudaGetSymbolAddress((void**)&Gl,  g_Gl);
    cudaGetSymbolAddress((void**)&PTh, g_PTh); cudaGetSymbolAddress((void**)&PTl, g_PTl);
    cudaGetSymbolAddress((void**)&RTh, g_RTh); cudaGetSymbolAddress((void**)&RTl, g_RTl);
    cudaGetSymbolAddress((void**)&Uh,  g_Uh);  cudaGetSymbolAddress((void**)&Ul,  g_Ul);
    cudaGetSymbolAddress((void**)&CTh, g_CTh); cudaGetSymbolAddress((void**)&CTl, g_CTl);
    cudaGetSymbolAddress((void**)&Wkbh,g_Wkbh);cudaGetSymbolAddress((void**)&Wkbl,g_Wkbl);
    cudaGetSymbolAddress((void**)&Wobh,g_Wobh);cudaGetSymbolAddress((void**)&Wobl,g_Wobl);
    cudaGetSymbolAddress((void**)&WvTh,g_WvTh);cudaGetSymbolAddress((void**)&WvTl,g_WvTl);
    cudaGetSymbolAddress((void**)&Wqbh,g_Wqbh);cudaGetSymbolAddress((void**)&Wqbl,g_Wqbl);
    cudaGetSymbolAddress((void**)&Gp,  g_Gp);  cudaGetSymbolAddress((void**)&Pp,  g_Pp);
    cudaGetSymbolAddress((void**)&Cp,  g_Cp);

    pack_all<<<12288, 256>>>(x, Wq, Wk, Wv, Wo);

    // G[n][m] = sum_l xT[n][l] xT[m][l]; split-K 8, fp32 partials
    gemm_bf3<128,128,0><<<dim3(4,4,16), 256, 65536>>>(
        xTh, xTl, xTh, xTl, Gp, nullptr, nullptr,
        512, LSEQ, LSEQ, 512,
        (long)bX, 512, (long)bX, 512, (long)(8*bS), (long)bS, 8);
    reduce_ns<8><<<512, 256>>>(Gp, Gh, Gl);

    // PT[c][n] = sum_m Wkb[c][m] G[n][m]  (G symmetric); split-K 4
    gemm_bf3<128,128,0><<<dim3(4,4,8), 256, 65536>>>(
        Wkbh, Wkbl, Gh, Gl, Pp, nullptr, nullptr,
        128, 512, 512, 512,
        0, 128, (long)bS, 128, (long)(4*bS), (long)bS, 4);
    reduce_ns<4><<<512, 256>>>(Pp, PTh, PTl);

    // RT[v][k](b,h) = sum_n WvT[hv][n] PT[hk][n]; batched (b,h)
    gemm_bf3<64,64,1><<<dim3(1,1,16), 256, 32768>>>(
        WvTh, WvTl, PTh, PTl, nullptr, RTh, RTl,
        512, 512, 512, 64,
        0, 32768, (long)bS, 32768, (long)(NH*4096), 4096, NH);

    // U[j][hv](b) = sum_k Wqb[hj][k] RT[v][k]; batched (b,h)
    gemm_bf3<128,64,1><<<dim3(1,4,16), 256, 49152>>>(
        Wqbh, Wqbl, RTh, RTl, nullptr, Uh, Ul,
        64, 64, 64, 512,
        0, 32768, (long)(NH*4096), 4096, (long)bS, 64, NH);

    // CT[o][j](b) = sum_hv Wob[o][hv] U[j][hv]; split-K 4
    gemm_bf3<128,128,0><<<dim3(4,4,8), 256, 65536>>>(
        Wobh, Wobl, Uh, Ul, Cp, nullptr, nullptr,
        128, 512, 512, 512,
        0, 128, (long)bS, 128, (long)(4*bS), (long)bS, 4);
    reduce_ns<4><<<512, 256>>>(Cp, CTh, CTl);

    // out[l][o] = sum_j x[l][j] CT[o][j]
    gemm_bf3<128,128,0><<<dim3(4,32,2), 256, 65536>>>(
        xh, xl, CTh, CTl, out, nullptr, nullptr,
        512, 512, 512, 512,
        (long)bX, 0, (long)bS, 0, (long)bX, 0, 1);
}

// round 6
// speedup vs baseline: 2.8981x; 1.0442x over previous
#include <cuda_runtime.h>
#include <cuda_bf16.h>
#include <cstdint>

#define LSEQ 4096
#define DIN  512
#define NH   8
#define NB   2

typedef unsigned short ushort_t;
static const size_t bS = 512 * 512;
static const size_t bX = (size_t)LSEQ * DIN;

// ---------------- device scratch ----------------
__device__ __align__(256) ushort_t g_xh [NB * LSEQ * DIN];
__device__ __align__(256) ushort_t g_xl [NB * LSEQ * DIN];
__device__ __align__(256) ushort_t g_xTh[NB * DIN * LSEQ];
__device__ __align__(256) ushort_t g_xTl[NB * DIN * LSEQ];
__device__ __align__(256) float    g_Gp [NB * 4 * 512 * 512];
__device__ __align__(256) ushort_t g_Gh [NB * 512 * 512];
__device__ __align__(256) ushort_t g_Gl [NB * 512 * 512];
__device__ __align__(256) float    g_Pp [NB * 4 * 512 * 512];
__device__ __align__(256) ushort_t g_PTh[NB * 512 * 512];
__device__ __align__(256) ushort_t g_PTl[NB * 512 * 512];
__device__ __align__(256) ushort_t g_RTh[NB * NH * 64 * 64];
__device__ __align__(256) ushort_t g_RTl[NB * NH * 64 * 64];
__device__ __align__(256) ushort_t g_Uh [NB * 512 * 512];
__device__ __align__(256) ushort_t g_Ul [NB * 512 * 512];
__device__ __align__(256) float    g_Cp [NB * 4 * 512 * 512];
__device__ __align__(256) ushort_t g_CTh[NB * 512 * 512];
__device__ __align__(256) ushort_t g_CTl[NB * 512 * 512];
__device__ __align__(256) ushort_t g_Wkbh[512 * 512];   // [c=h*64+k][m]
__device__ __align__(256) ushort_t g_Wkbl[512 * 512];
__device__ __align__(256) ushort_t g_Wobh[512 * 512];   // [o][hv]
__device__ __align__(256) ushort_t g_Wobl[512 * 512];
__device__ __align__(256) ushort_t g_WvTh[512 * 512];   // [hv][n]
__device__ __align__(256) ushort_t g_WvTl[512 * 512];
__device__ __align__(256) ushort_t g_Wqbh[512 * 64 * NH]; // [h*512+j][k]
__device__ __align__(256) ushort_t g_Wqbl[512 * 64 * NH];

// ---------------- helpers ----------------
#define SWZ(o) ((o) ^ (((o) >> 3) & 0x70))

__device__ __forceinline__ uint32_t smem_u32(const void* p) {
    uint32_t a;
    asm("{ .reg .u64 t; cvta.to.shared.u64 t, %1; cvt.u32.u64 %0, t; }" : "=r"(a) : "l"(p));
    return a;
}
__device__ __forceinline__ ushort_t f2bf(float v) {
    __nv_bfloat16 b = __float2bfloat16(v);
    return *reinterpret_cast<ushort_t*>(&b);
}
__device__ __forceinline__ float bfhi(ushort_t h) {
    return __uint_as_float(((uint32_t)h) << 16);
}
__device__ __forceinline__ void ldsm4(uint32_t* f, uint32_t addr) {
    asm volatile("ldmatrix.sync.aligned.m8n8.x4.shared.b16 {%0,%1,%2,%3}, [%4];"
                 : "=r"(f[0]), "=r"(f[1]), "=r"(f[2]), "=r"(f[3]) : "r"(addr));
}
__device__ __forceinline__ void mma16816(float* d, const uint32_t* a, const uint32_t* b) {
    asm volatile("mma.sync.aligned.m16n8k16.row.col.f32.bf16.bf16.f32 "
                 "{%0,%1,%2,%3}, {%4,%5,%6,%7}, {%8,%9}, {%0,%1,%2,%3};"
                 : "+f"(d[0]), "+f"(d[1]), "+f"(d[2]), "+f"(d[3])
                 : "r"(a[0]), "r"(a[1]), "r"(a[2]), "r"(a[3]), "r"(b[0]), "r"(b[1]));
}
__device__ __forceinline__ void cpa16(uint32_t s, const void* g) {
    asm volatile("cp.async.cg.shared.global [%0], [%1], 16;" :: "r"(s), "l"(g) : "memory");
}
#define CP_COMMIT() asm volatile("cp.async.commit_group;" ::: "memory")
#define CP_WAIT(n)  asm volatile("cp.async.wait_group %0;" :: "n"(n) : "memory")

// ===========================================================================
// Generic bf16x3 GEMM via mma.sync (HMMA): C(m,n) = sum_k A(m,k)*B(n,k).
// A, B pre-split bf16 hi/lo, K contiguous. 256 threads, warp grid 2(m)x4(n).
// 4-stage cp.async pipeline, ONE __syncthreads per ktile.
// EPI 0: fp32 row-major out. EPI 1: bf16 hi/lo row-major out.
// ===========================================================================
template <int BM, int BN, int EPI>
__global__ void __launch_bounds__(256, 1)
gemm_bf3(const ushort_t* __restrict__ Ah, const ushort_t* __restrict__ Al,
         const ushort_t* __restrict__ Bh, const ushort_t* __restrict__ Bl,
         float* __restrict__ Cf, ushort_t* __restrict__ Ch, ushort_t* __restrict__ Cl,
         int K, int lda, int ldb, int ldc,
         long bA, long slA, long bB, long slB, long bC, long slC, int nsl) {
    constexpr int WM = BM / 2, WN = BN / 4;
    constexpr int MT = WM / 16, NT = WN / 8, PB = WN / 16;
    constexpr int SS = (BM + BN) * 128;          // stage bytes: Ah|Al|Bh|Bl
    constexpr int NSTG = 4;

    extern __shared__ char dsm[];
    uint32_t sb = smem_u32(dsm);
    int tid = threadIdx.x, lane = tid & 31, wid = tid >> 5;
    int wm = wid & 1, wn = wid >> 1;

    int z = blockIdx.z, b = z / nsl, sl = z - b * nsl;
    int m0 = blockIdx.y * BM, n0 = blockIdx.x * BN;
    const ushort_t* pAh = Ah + b * bA + sl * slA + (size_t)m0 * lda;
    const ushort_t* pAl = Al + b * bA + sl * slA + (size_t)m0 * lda;
    const ushort_t* pBh = Bh + b * bB + sl * slB + (size_t)n0 * ldb;
    const ushort_t* pBl = Bl + b * bB + sl * slB + (size_t)n0 * ldb;

    float acc[MT][NT][4];
#pragma unroll
    for (int i = 0; i < MT; i++)
#pragma unroll
        for (int j = 0; j < NT; j++)
#pragma unroll
            for (int q = 0; q < 4; q++) acc[i][j][q] = 0.f;

    const int nkt = K >> 5;

    auto load_stage = [&](int stg, int kt, bool pred) {
        if (pred) {
            uint32_t s0 = sb + stg * SS;
            int ke = kt * 32;
#pragma unroll
            for (int c = tid; c < BM * 4; c += 256) {
                int r = c >> 2, sg = c & 3;
                uint32_t o = SWZ((uint32_t)((r >> 1) * 128 + (r & 1) * 64 + sg * 16));
                cpa16(s0 + o,           pAh + (size_t)r * lda + ke + sg * 8);
                cpa16(s0 + BM * 64 + o, pAl + (size_t)r * lda + ke + sg * 8);
            }
#pragma unroll
            for (int c = tid; c < BN * 4; c += 256) {
                int r = c >> 2, sg = c & 3;
                uint32_t o = SWZ((uint32_t)((r >> 1) * 128 + (r & 1) * 64 + sg * 16));
                cpa16(s0 + BM * 128 + o,           pBh + (size_t)r * ldb + ke + sg * 8);
                cpa16(s0 + BM * 128 + BN * 64 + o, pBl + (size_t)r * ldb + ke + sg * 8);
            }
        }
        CP_COMMIT();
    };

    // prologue: stages 0..2
#pragma unroll
    for (int s = 0; s < NSTG - 1; s++) load_stage(s, s, s < nkt);

#pragma unroll 1
    for (int kt = 0; kt < nkt; kt++) {
        CP_WAIT(2);
        __syncthreads();
        // prefetch stage kt+3 into slot (kt+3)%4 == slot of kt-1 (safe: the
        // sync above proves all warps finished computing ktile kt-1)
        load_stage((kt + NSTG - 1) & (NSTG - 1), kt + NSTG - 1, kt + NSTG - 1 < nkt);

        uint32_t stb = sb + (kt & (NSTG - 1)) * SS;
#pragma unroll
        for (int ks = 0; ks < 2; ks++) {
            uint32_t ah[MT][4], al[MT][4], bh[PB][4], bl[PB][4];
            int ar  = wm * WM + (lane & 15);
            int akk = ks * 16 + (lane >> 4) * 8;
#pragma unroll
            for (int mt = 0; mt < MT; mt++) {
                int r = ar + mt * 16;
                uint32_t o = SWZ((uint32_t)((r >> 1) * 128 + (r & 1) * 64 + akk * 2));
                ldsm4(ah[mt], stb + o);
                ldsm4(al[mt], stb + BM * 64 + o);
            }
            int bn  = wn * WN + (lane & 7) + ((lane >> 4) & 1) * 8;
            int bkk = ks * 16 + ((lane >> 3) & 1) * 8;
#pragma unroll
            for (int p = 0; p < PB; p++) {
                int r = bn + p * 16;
                uint32_t o = SWZ((uint32_t)((r >> 1) * 128 + (r & 1) * 64 + bkk * 2));
                ldsm4(bh[p], stb + BM * 128 + o);
                ldsm4(bl[p], stb + BM * 128 + BN * 64 + o);
            }
#pragma unroll
            for (int mt = 0; mt < MT; mt++)
#pragma unroll
                for (int nt = 0; nt < NT; nt++) {
                    const uint32_t* fh = &bh[nt >> 1][(nt & 1) * 2];
                    const uint32_t* fl = &bl[nt >> 1][(nt & 1) * 2];
                    mma16816(acc[mt][nt], ah[mt], fh);
                    mma16816(acc[mt][nt], al[mt], fh);
                    mma16816(acc[mt][nt], ah[mt], fl);
                }
        }
    }

    long offC = b * bC + sl * slC;
    int r0 = m0 + wm * WM + (lane >> 2);
    int c0 = n0 + wn * WN + (lane & 3) * 2;
    if (EPI == 0) {
        float* Co = Cf + offC;
#pragma unroll
        for (int mt = 0; mt < MT; mt++)
#pragma unroll
            for (int nt = 0; nt < NT; nt++) {
                int r = r0 + mt * 16, c = c0 + nt * 8;
                *(float2*)&Co[(size_t)r * ldc + c] =
                    make_float2(acc[mt][nt][0], acc[mt][nt][1]);
                *(float2*)&Co[(size_t)(r + 8) * ldc + c] =
                    make_float2(acc[mt][nt][2], acc[mt][nt][3]);
            }
    } else {
        ushort_t* Hh = Ch + offC;
        ushort_t* Hl = Cl + offC;
#pragma unroll
        for (int mt = 0; mt < MT; mt++)
#pragma unroll
            for (int nt = 0; nt < NT; nt++)
#pragma unroll
                for (int hf = 0; hf < 2; hf++) {
                    int r = r0 + mt * 16 + hf * 8, c = c0 + nt * 8;
                    float v0 = acc[mt][nt][hf * 2], v1 = acc[mt][nt][hf * 2 + 1];
                    ushort_t h0 = f2bf(v0), h1 = f2bf(v1);
                    *(ushort2*)&Hh[(size_t)r * ldc + c] = make_ushort2(h0, h1);
                    *(ushort2*)&Hl[(size_t)r * ldc + c] =
                        make_ushort2(f2bf(v0 - bfhi(h0)), f2bf(v1 - bfhi(h1)));
                }
    }
}

// ===========================================================================
// Fused input pack
// ===========================================================================
__global__ void pack_all(const float* __restrict__ x, const float* __restrict__ Wq,
                         const float* __restrict__ Wk, const float* __restrict__ Wv,
                         const float* __restrict__ Wo) {
    __shared__ float s[32][33];
    int blk = blockIdx.x, tid = threadIdx.x;
    if (blk < 4096) {                      // x row-major split
        size_t i = (size_t)blk * 256 + tid;
        float4 v = ((const float4*)x)[i];
        ushort_t h0 = f2bf(v.x), h1 = f2bf(v.y), h2 = f2bf(v.z), h3 = f2bf(v.w);
        ((ushort4*)g_xh)[i] = make_ushort4(h0, h1, h2, h3);
        ((ushort4*)g_xl)[i] = make_ushort4(f2bf(v.x - bfhi(h0)), f2bf(v.y - bfhi(h1)),
                                           f2bf(v.z - bfhi(h2)), f2bf(v.w - bfhi(h3)));
    } else if (blk < 8192) {               // x transpose -> xT[d][l]
        int id = blk - 4096;
        int bx = id & 127, by = (id >> 7) & 15, b = id >> 11;
        int r0 = bx * 32, c0 = by * 32;
        int tx = tid & 31, ty = tid >> 5;
        const float* xb = x + (size_t)b * bX;
#pragma unroll
        for (int q = 0; q < 4; q++)
            s[ty + 8 * q][tx] = xb[(size_t)(r0 + ty + 8 * q) * DIN + c0 + tx];
        __syncthreads();
#pragma unroll
        for (int q = 0; q < 4; q++) {
            int cd = ty + 8 * q;
            float v = s[tx][cd];
            ushort_t h = f2bf(v);
            size_t o = ((size_t)b * DIN + c0 + cd) * LSEQ + r0 + tx;
            g_xTh[o] = h;
            g_xTl[o] = f2bf(v - bfhi(h));
        }
    } else if (blk < 9216) {               // Wkb[c][m] = Wk[h][m][k]
        int i = (blk - 8192) * 256 + tid;
        int c = i >> 9, m = i & 511, h = c >> 6, kd = c & 63;
        float v = Wk[h * 32768 + m * 64 + kd];
        ushort_t hh = f2bf(v);
        g_Wkbh[i] = hh; g_Wkbl[i] = f2bf(v - bfhi(hh));
    } else if (blk < 10240) {              // Wob[o][hv] = Wo[hv][o]
        int i = (blk - 9216) * 256 + tid;
        int o = i >> 9, hv = i & 511;
        float v = Wo[hv * 512 + o];
        ushort_t hh = f2bf(v);
        g_Wobh[i] = hh; g_Wobl[i] = f2bf(v - bfhi(hh));
    } else if (blk < 11264) {              // WvT[hv][n] = Wv[h][n][v]
        int i = (blk - 10240) * 256 + tid;
        int row = i >> 9, n = i & 511, h = row >> 6, vv = row & 63;
        float v = Wv[h * 32768 + n * 64 + vv];
        ushort_t hh = f2bf(v);
        g_WvTh[i] = hh; g_WvTl[i] = f2bf(v - bfhi(hh));
    } else {                               // Wqb straight split
        int i = (blk - 11264) * 256 + tid;
        float v = Wq[i];
        ushort_t hh = f2bf(v);
        g_Wqbh[i] = hh; g_Wqbl[i] = f2bf(v - bfhi(hh));
    }
}

// ===========================================================================
// Split-K reduce: sum NS fp32 partials per batch, emit bf16 hi/lo.
// ===========================================================================
template <int NS>
__global__ void reduce_ns(const float* __restrict__ src,
                          ushort_t* __restrict__ oh, ushort_t* __restrict__ ol) {
    int i = blockIdx.x * 256 + threadIdx.x;          // over NB*65536 float4
    int b = i >> 16, e = i & 65535;
    const float4* p = (const float4*)src;
    float4 v = p[(size_t)(b * NS) * 65536 + e];
#pragma unroll
    for (int q = 1; q < NS; q++) {
        float4 t = p[(size_t)(b * NS + q) * 65536 + e];
        v.x += t.x; v.y += t.y; v.z += t.z; v.w += t.w;
    }
    ushort_t h0 = f2bf(v.x), h1 = f2bf(v.y), h2 = f2bf(v.z), h3 = f2bf(v.w);
    size_t o = (size_t)b * 65536 + e;
    ((ushort4*)oh)[o] = make_ushort4(h0, h1, h2, h3);
    ((ushort4*)ol)[o] = make_ushort4(f2bf(v.x - bfhi(h0)), f2bf(v.y - bfhi(h1)),
                                     f2bf(v.z - bfhi(h2)), f2bf(v.w - bfhi(h3)));
}

// ===========================================================================
extern "C" void kernel_launch(void* const* d_in, const int* in_sizes, int n_in,
                              void* d_out, int out_size) {
    const float* x  = (const float*)d_in[0];
    const float* Wq = (const float*)d_in[1];
    const float* Wk = (const float*)d_in[2];
    const float* Wv = (const float*)d_in[3];
    const float* Wo = (const float*)d_in[4];
    float* out = (float*)d_out;

    cudaFuncSetAttribute(gemm_bf3<128,128,0>, cudaFuncAttributeMaxDynamicSharedMemorySize, 131072);
    cudaFuncSetAttribute(gemm_bf3<64,64,1>,   cudaFuncAttributeMaxDynamicSharedMemorySize, 65536);
    cudaFuncSetAttribute(gemm_bf3<128,64,1>,  cudaFuncAttributeMaxDynamicSharedMemorySize, 98304);

    ushort_t *xh,*xl,*xTh,*xTl,*Gh,*Gl,*PTh,*PTl,*RTh,*RTl,*Uh,*Ul,*CTh,*CTl;
    ushort_t *Wkbh,*Wkbl,*Wobh,*Wobl,*WvTh,*WvTl,*Wqbh,*Wqbl;
    float *Gp,*Pp,*Cp;
    cudaGetSymbolAddress((void**)&xh,  g_xh);  cudaGetSymbolAddress((void**)&xl,  g_xl);
    cudaGetSymbolAddress((void**)&xTh, g_xTh); cudaGetSymbolAddress((void**)&xTl, g_xTl);
    cudaGetSymbolAddress((void**)&Gh,  g_Gh);  cudaGetSymbolAddress((void**)&Gl,  g_Gl);
    cudaGetSymbolAddress((void**)&PTh, g_PTh); cudaGetSymbolAddress((void**)&PTl, g_PTl);
    cudaGetSymbolAddress((void**)&RTh, g_RTh); cudaGetSymbolAddress((void**)&RTl, g_RTl);
    cudaGetSymbolAddress((void**)&Uh,  g_Uh);  cudaGetSymbolAddress((void**)&Ul,  g_Ul);
    cudaGetSymbolAddress((void**)&CTh, g_CTh); cudaGetSymbolAddress((void**)&CTl, g_CTl);
    cudaGetSymbolAddress((void**)&Wkbh,g_Wkbh);cudaGetSymbolAddress((void**)&Wkbl,g_Wkbl);
    cudaGetSymbolAddress((void**)&Wobh,g_Wobh);cudaGetSymbolAddress((void**)&Wobl,g_Wobl);
    cudaGetSymbolAddress((void**)&WvTh,g_WvTh);cudaGetSymbolAddress((void**)&WvTl,g_WvTl);
    cudaGetSymbolAddress((void**)&Wqbh,g_Wqbh);cudaGetSymbolAddress((void**)&Wqbl,g_Wqbl);
    cudaGetSymbolAddress((void**)&Gp,  g_Gp);  cudaGetSymbolAddress((void**)&Pp,  g_Pp);
    cudaGetSymbolAddress((void**)&Cp,  g_Cp);

    pack_all<<<12288, 256>>>(x, Wq, Wk, Wv, Wo);

    // G[n][m] = sum_l xT[n][l] xT[m][l]; split-K 4, fp32 partials
    gemm_bf3<128,128,0><<<dim3(4,4,8), 256, 131072>>>(
        xTh, xTl, xTh, xTl, Gp, nullptr, nullptr,
        1024, LSEQ, LSEQ, 512,
        (long)bX, 1024, (long)bX, 1024, (long)(4*bS), (long)bS, 4);
    reduce_ns<4><<<512, 256>>>(Gp, Gh, Gl);

    // PT[c][n] = sum_m Wkb[c][m] G[n][m]  (G symmetric); split-K 4
    gemm_bf3<128,128,0><<<dim3(4,4,8), 256, 131072>>>(
        Wkbh, Wkbl, Gh, Gl, Pp, nullptr, nullptr,
        128, 512, 512, 512,
        0, 128, (long)bS, 128, (long)(4*bS), (long)bS, 4);
    reduce_ns<4><<<512, 256>>>(Pp, PTh, PTl);

    // RT[v][k](b,h) = sum_n WvT[hv][n] PT[hk][n]; batched (b,h)
    gemm_bf3<64,64,1><<<dim3(1,1,16), 256, 65536>>>(
        WvTh, WvTl, PTh, PTl, nullptr, RTh, RTl,
        512, 512, 512, 64,
        0, 32768, (long)bS, 32768, (long)(NH*4096), 4096, NH);

    // U[j][hv](b) = sum_k Wqb[hj][k] RT[v][k]; batched (b,h)
    gemm_bf3<128,64,1><<<dim3(1,4,16), 256, 98304>>>(
        Wqbh, Wqbl, RTh, RTl, nullptr, Uh, Ul,
        64, 64, 64, 512,
        0, 32768, (long)(NH*4096), 4096, (long)bS, 64, NH);

    // CT[o][j](b) = sum_hv Wob[o][hv] U[j][hv]; split-K 4
    gemm_bf3<128,128,0><<<dim3(4,4,8), 256, 131072>>>(
        Wobh, Wobl, Uh, Ul, Cp, nullptr, nullptr,
        128, 512, 512, 512,
        0, 128, (long)bS, 128, (long)(4*bS), (long)bS, 4);
    reduce_ns<4><<<512, 256>>>(Cp, CTh, CTl);

    // out[l][o] = sum_j x[l][j] CT[o][j]
    gemm_bf3<128,128,0><<<dim3(4,32,2), 256, 131072>>>(
        xh, xl, CTh, CTl, out, nullptr, nullptr,
        512, 512, 512, 512,
        (long)bX, 0, (long)bS, 0, (long)bX, 0, 1);
}

// round 7
// speedup vs baseline: 2.9163x; 1.0063x over previous
#include <cuda_runtime.h>
#include <cuda_bf16.h>
#include <cstdint>

#define LSEQ 4096
#define DIN  512
#define NH   8
#define NB   2

typedef unsigned short ushort_t;
static const size_t bS = 512 * 512;
static const size_t bX = (size_t)LSEQ * DIN;

// ---------------- device scratch ----------------
__device__ __align__(256) ushort_t g_xh [NB * LSEQ * DIN];
__device__ __align__(256) ushort_t g_xl [NB * LSEQ * DIN];
__device__ __align__(256) ushort_t g_xTh[NB * DIN * LSEQ];
__device__ __align__(256) ushort_t g_xTl[NB * DIN * LSEQ];
__device__ __align__(256) float    g_Gp [NB * 4 * 512 * 512];
__device__ __align__(256) ushort_t g_Gh [NB * 512 * 512];
__device__ __align__(256) ushort_t g_Gl [NB * 512 * 512];
__device__ __align__(256) float    g_Pp [NB * 4 * 512 * 512];
__device__ __align__(256) ushort_t g_PTh[NB * 512 * 512];
__device__ __align__(256) ushort_t g_PTl[NB * 512 * 512];
__device__ __align__(256) ushort_t g_RTh[NB * NH * 64 * 64];
__device__ __align__(256) ushort_t g_RTl[NB * NH * 64 * 64];
__device__ __align__(256) ushort_t g_Uh [NB * 512 * 512];
__device__ __align__(256) ushort_t g_Ul [NB * 512 * 512];
__device__ __align__(256) float    g_Cp [NB * 4 * 512 * 512];
__device__ __align__(256) ushort_t g_CTh[NB * 512 * 512];
__device__ __align__(256) ushort_t g_CTl[NB * 512 * 512];
__device__ __align__(256) ushort_t g_Wkbh[512 * 512];   // [c=h*64+k][m]
__device__ __align__(256) ushort_t g_Wkbl[512 * 512];
__device__ __align__(256) ushort_t g_Wobh[512 * 512];   // [o][hv]
__device__ __align__(256) ushort_t g_Wobl[512 * 512];
__device__ __align__(256) ushort_t g_WvTh[512 * 512];   // [hv][n]
__device__ __align__(256) ushort_t g_WvTl[512 * 512];
__device__ __align__(256) ushort_t g_Wqbh[512 * 64 * NH]; // [h*512+j][k]
__device__ __align__(256) ushort_t g_Wqbl[512 * 64 * NH];

// ---------------- helpers ----------------
#define SWZ(o) ((o) ^ (((o) >> 3) & 0x70))

__device__ __forceinline__ uint32_t smem_u32(const void* p) {
    uint32_t a;
    asm("{ .reg .u64 t; cvta.to.shared.u64 t, %1; cvt.u32.u64 %0, t; }" : "=r"(a) : "l"(p));
    return a;
}
__device__ __forceinline__ ushort_t f2bf(float v) {
    __nv_bfloat16 b = __float2bfloat16(v);
    return *reinterpret_cast<ushort_t*>(&b);
}
__device__ __forceinline__ float bfhi(ushort_t h) {
    return __uint_as_float(((uint32_t)h) << 16);
}
__device__ __forceinline__ void ldsm4(uint32_t* f, uint32_t addr) {
    asm volatile("ldmatrix.sync.aligned.m8n8.x4.shared.b16 {%0,%1,%2,%3}, [%4];"
                 : "=r"(f[0]), "=r"(f[1]), "=r"(f[2]), "=r"(f[3]) : "r"(addr));
}
__device__ __forceinline__ void mma16816(float* d, const uint32_t* a, const uint32_t* b) {
    asm volatile("mma.sync.aligned.m16n8k16.row.col.f32.bf16.bf16.f32 "
                 "{%0,%1,%2,%3}, {%4,%5,%6,%7}, {%8,%9}, {%0,%1,%2,%3};"
                 : "+f"(d[0]), "+f"(d[1]), "+f"(d[2]), "+f"(d[3])
                 : "r"(a[0]), "r"(a[1]), "r"(a[2]), "r"(a[3]), "r"(b[0]), "r"(b[1]));
}
__device__ __forceinline__ void cpa16(uint32_t s, const void* g) {
    asm volatile("cp.async.cg.shared.global [%0], [%1], 16;" :: "r"(s), "l"(g) : "memory");
}
#define CP_COMMIT() asm volatile("cp.async.commit_group;" ::: "memory")
#define CP_WAIT(n)  asm volatile("cp.async.wait_group %0;" :: "n"(n) : "memory")

// ===========================================================================
// Generic bf16x3 GEMM via mma.sync (HMMA): C(m,n) = sum_k A(m,k)*B(n,k).
// A, B pre-split bf16 hi/lo, K contiguous. 256 threads, warp grid 2(m)x4(n).
// 4-stage cp.async pipeline, ONE __syncthreads per ktile.
// EPI 0: fp32 row-major out. EPI 1: bf16 hi/lo row-major out.
// ===========================================================================
template <int BM, int BN, int EPI>
__global__ void __launch_bounds__(256, 1)
gemm_bf3(const ushort_t* __restrict__ Ah, const ushort_t* __restrict__ Al,
         const ushort_t* __restrict__ Bh, const ushort_t* __restrict__ Bl,
         float* __restrict__ Cf, ushort_t* __restrict__ Ch, ushort_t* __restrict__ Cl,
         int K, int lda, int ldb, int ldc,
         long bA, long slA, long bB, long slB, long bC, long slC, int nsl) {
    constexpr int WM = BM / 2, WN = BN / 4;
    constexpr int MT = WM / 16, NT = WN / 8, PB = WN / 16;
    constexpr int SS = (BM + BN) * 128;          // stage bytes: Ah|Al|Bh|Bl
    constexpr int NSTG = 4;

    extern __shared__ char dsm[];
    uint32_t sb = smem_u32(dsm);
    int tid = threadIdx.x, lane = tid & 31, wid = tid >> 5;
    int wm = wid & 1, wn = wid >> 1;

    int z = blockIdx.z, b = z / nsl, sl = z - b * nsl;
    int m0 = blockIdx.y * BM, n0 = blockIdx.x * BN;
    const ushort_t* pAh = Ah + b * bA + sl * slA + (size_t)m0 * lda;
    const ushort_t* pAl = Al + b * bA + sl * slA + (size_t)m0 * lda;
    const ushort_t* pBh = Bh + b * bB + sl * slB + (size_t)n0 * ldb;
    const ushort_t* pBl = Bl + b * bB + sl * slB + (size_t)n0 * ldb;

    float acc[MT][NT][4];
#pragma unroll
    for (int i = 0; i < MT; i++)
#pragma unroll
        for (int j = 0; j < NT; j++)
#pragma unroll
            for (int q = 0; q < 4; q++) acc[i][j][q] = 0.f;

    const int nkt = K >> 5;

    auto load_stage = [&](int stg, int kt, bool pred) {
        if (pred) {
            uint32_t s0 = sb + stg * SS;
            int ke = kt * 32;
#pragma unroll
            for (int c = tid; c < BM * 4; c += 256) {
                int r = c >> 2, sg = c & 3;
                uint32_t o = SWZ((uint32_t)((r >> 1) * 128 + (r & 1) * 64 + sg * 16));
                cpa16(s0 + o,           pAh + (size_t)r * lda + ke + sg * 8);
                cpa16(s0 + BM * 64 + o, pAl + (size_t)r * lda + ke + sg * 8);
            }
#pragma unroll
            for (int c = tid; c < BN * 4; c += 256) {
                int r = c >> 2, sg = c & 3;
                uint32_t o = SWZ((uint32_t)((r >> 1) * 128 + (r & 1) * 64 + sg * 16));
                cpa16(s0 + BM * 128 + o,           pBh + (size_t)r * ldb + ke + sg * 8);
                cpa16(s0 + BM * 128 + BN * 64 + o, pBl + (size_t)r * ldb + ke + sg * 8);
            }
        }
        CP_COMMIT();
    };

    // prologue: stages 0..2
#pragma unroll
    for (int s = 0; s < NSTG - 1; s++) load_stage(s, s, s < nkt);

#pragma unroll 1
    for (int kt = 0; kt < nkt; kt++) {
        CP_WAIT(2);
        __syncthreads();
        // prefetch stage kt+3 into slot (kt+3)%4 == slot of kt-1 (safe: the
        // sync above proves all warps finished computing ktile kt-1)
        load_stage((kt + NSTG - 1) & (NSTG - 1), kt + NSTG - 1, kt + NSTG - 1 < nkt);

        uint32_t stb = sb + (kt & (NSTG - 1)) * SS;
#pragma unroll
        for (int ks = 0; ks < 2; ks++) {
            uint32_t ah[MT][4], al[MT][4], bh[PB][4], bl[PB][4];
            int ar  = wm * WM + (lane & 15);
            int akk = ks * 16 + (lane >> 4) * 8;
#pragma unroll
            for (int mt = 0; mt < MT; mt++) {
                int r = ar + mt * 16;
                uint32_t o = SWZ((uint32_t)((r >> 1) * 128 + (r & 1) * 64 + akk * 2));
                ldsm4(ah[mt], stb + o);
                ldsm4(al[mt], stb + BM * 64 + o);
            }
            int bn  = wn * WN + (lane & 7) + ((lane >> 4) & 1) * 8;
            int bkk = ks * 16 + ((lane >> 3) & 1) * 8;
#pragma unroll
            for (int p = 0; p < PB; p++) {
                int r = bn + p * 16;
                uint32_t o = SWZ((uint32_t)((r >> 1) * 128 + (r & 1) * 64 + bkk * 2));
                ldsm4(bh[p], stb + BM * 128 + o);
                ldsm4(bl[p], stb + BM * 128 + BN * 64 + o);
            }
#pragma unroll
            for (int mt = 0; mt < MT; mt++)
#pragma unroll
                for (int nt = 0; nt < NT; nt++) {
                    const uint32_t* fh = &bh[nt >> 1][(nt & 1) * 2];
                    const uint32_t* fl = &bl[nt >> 1][(nt & 1) * 2];
                    mma16816(acc[mt][nt], ah[mt], fh);
                    mma16816(acc[mt][nt], al[mt], fh);
                    mma16816(acc[mt][nt], ah[mt], fl);
                }
        }
    }

    long offC = b * bC + sl * slC;
    int r0 = m0 + wm * WM + (lane >> 2);
    int c0 = n0 + wn * WN + (lane & 3) * 2;
    if (EPI == 0) {
        float* Co = Cf + offC;
#pragma unroll
        for (int mt = 0; mt < MT; mt++)
#pragma unroll
            for (int nt = 0; nt < NT; nt++) {
                int r = r0 + mt * 16, c = c0 + nt * 8;
                *(float2*)&Co[(size_t)r * ldc + c] =
                    make_float2(acc[mt][nt][0], acc[mt][nt][1]);
                *(float2*)&Co[(size_t)(r + 8) * ldc + c] =
                    make_float2(acc[mt][nt][2], acc[mt][nt][3]);
            }
    } else {
        ushort_t* Hh = Ch + offC;
        ushort_t* Hl = Cl + offC;
#pragma unroll
        for (int mt = 0; mt < MT; mt++)
#pragma unroll
            for (int nt = 0; nt < NT; nt++)
#pragma unroll
                for (int hf = 0; hf < 2; hf++) {
                    int r = r0 + mt * 16 + hf * 8, c = c0 + nt * 8;
                    float v0 = acc[mt][nt][hf * 2], v1 = acc[mt][nt][hf * 2 + 1];
                    ushort_t h0 = f2bf(v0), h1 = f2bf(v1);
                    *(ushort2*)&Hh[(size_t)r * ldc + c] = make_ushort2(h0, h1);
                    *(ushort2*)&Hl[(size_t)r * ldc + c] =
                        make_ushort2(f2bf(v0 - bfhi(h0)), f2bf(v1 - bfhi(h1)));
                }
    }
}

// ===========================================================================
// Fused input pack
// ===========================================================================
__global__ void pack_all(const float* __restrict__ x, const float* __restrict__ Wq,
                         const float* __restrict__ Wk, const float* __restrict__ Wv,
                         const float* __restrict__ Wo) {
    __shared__ float s[32][33];
    int blk = blockIdx.x, tid = threadIdx.x;
    if (blk < 4096) {                      // x row-major split
        size_t i = (size_t)blk * 256 + tid;
        float4 v = ((const float4*)x)[i];
        ushort_t h0 = f2bf(v.x), h1 = f2bf(v.y), h2 = f2bf(v.z), h3 = f2bf(v.w);
        ((ushort4*)g_xh)[i] = make_ushort4(h0, h1, h2, h3);
        ((ushort4*)g_xl)[i] = make_ushort4(f2bf(v.x - bfhi(h0)), f2bf(v.y - bfhi(h1)),
                                           f2bf(v.z - bfhi(h2)), f2bf(v.w - bfhi(h3)));
    } else if (blk < 8192) {               // x transpose -> xT[d][l]
        int id = blk - 4096;
        int bx = id & 127, by = (id >> 7) & 15, b = id >> 11;
        int r0 = bx * 32, c0 = by * 32;
        int tx = tid & 31, ty = tid >> 5;
        const float* xb = x + (size_t)b * bX;
#pragma unroll
        for (int q = 0; q < 4; q++)
            s[ty + 8 * q][tx] = xb[(size_t)(r0 + ty + 8 * q) * DIN + c0 + tx];
        __syncthreads();
#pragma unroll
        for (int q = 0; q < 4; q++) {
            int cd = ty + 8 * q;
            float v = s[tx][cd];
            ushort_t h = f2bf(v);
            size_t o = ((size_t)b * DIN + c0 + cd) * LSEQ + r0 + tx;
            g_xTh[o] = h;
            g_xTl[o] = f2bf(v - bfhi(h));
        }
    } else if (blk < 9216) {               // Wkb[c][m] = Wk[h][m][k]
        int i = (blk - 8192) * 256 + tid;
        int c = i >> 9, m = i & 511, h = c >> 6, kd = c & 63;
        float v = Wk[h * 32768 + m * 64 + kd];
        ushort_t hh = f2bf(v);
        g_Wkbh[i] = hh; g_Wkbl[i] = f2bf(v - bfhi(hh));
    } else if (blk < 10240) {              // Wob[o][hv] = Wo[hv][o]
        int i = (blk - 9216) * 256 + tid;
        int o = i >> 9, hv = i & 511;
        float v = Wo[hv * 512 + o];
        ushort_t hh = f2bf(v);
        g_Wobh[i] = hh; g_Wobl[i] = f2bf(v - bfhi(hh));
    } else if (blk < 11264) {              // WvT[hv][n] = Wv[h][n][v]
        int i = (blk - 10240) * 256 + tid;
        int row = i >> 9, n = i & 511, h = row >> 6, vv = row & 63;
        float v = Wv[h * 32768 + n * 64 + vv];
        ushort_t hh = f2bf(v);
        g_WvTh[i] = hh; g_WvTl[i] = f2bf(v - bfhi(hh));
    } else {                               // Wqb straight split
        int i = (blk - 11264) * 256 + tid;
        float v = Wq[i];
        ushort_t hh = f2bf(v);
        g_Wqbh[i] = hh; g_Wqbl[i] = f2bf(v - bfhi(hh));
    }
}

// ===========================================================================
// Split-K reduce: sum NS fp32 partials per batch, emit bf16 hi/lo.
// ===========================================================================
template <int NS>
__global__ void reduce_ns(const float* __restrict__ src,
                          ushort_t* __restrict__ oh, ushort_t* __restrict__ ol) {
    int i = blockIdx.x * 256 + threadIdx.x;          // over NB*65536 float4
    int b = i >> 16, e = i & 65535;
    const float4* p = (const float4*)src;
    float4 v = p[(size_t)(b * NS) * 65536 + e];
#pragma unroll
    for (int q = 1; q < NS; q++) {
        float4 t = p[(size_t)(b * NS + q) * 65536 + e];
        v.x += t.x; v.y += t.y; v.z += t.z; v.w += t.w;
    }
    ushort_t h0 = f2bf(v.x), h1 = f2bf(v.y), h2 = f2bf(v.z), h3 = f2bf(v.w);
    size_t o = (size_t)b * 65536 + e;
    ((ushort4*)oh)[o] = make_ushort4(h0, h1, h2, h3);
    ((ushort4*)ol)[o] = make_ushort4(f2bf(v.x - bfhi(h0)), f2bf(v.y - bfhi(h1)),
                                     f2bf(v.z - bfhi(h2)), f2bf(v.w - bfhi(h3)));
}

// ===========================================================================
extern "C" void kernel_launch(void* const* d_in, const int* in_sizes, int n_in,
                              void* d_out, int out_size) {
    const float* x  = (const float*)d_in[0];
    const float* Wq = (const float*)d_in[1];
    const float* Wk = (const float*)d_in[2];
    const float* Wv = (const float*)d_in[3];
    const float* Wo = (const float*)d_in[4];
    float* out = (float*)d_out;

    cudaFuncSetAttribute(gemm_bf3<128,128,0>, cudaFuncAttributeMaxDynamicSharedMemorySize, 131072);
    cudaFuncSetAttribute(gemm_bf3<64,64,1>,   cudaFuncAttributeMaxDynamicSharedMemorySize, 65536);
    cudaFuncSetAttribute(gemm_bf3<128,64,1>,  cudaFuncAttributeMaxDynamicSharedMemorySize, 98304);

    ushort_t *xh,*xl,*xTh,*xTl,*Gh,*Gl,*PTh,*PTl,*RTh,*RTl,*Uh,*Ul,*CTh,*CTl;
    ushort_t *Wkbh,*Wkbl,*Wobh,*Wobl,*WvTh,*WvTl,*Wqbh,*Wqbl;
    float *Gp,*Pp,*Cp;
    cudaGetSymbolAddress((void**)&xh,  g_xh);  cudaGetSymbolAddress((void**)&xl,  g_xl);
    cudaGetSymbolAddress((void**)&xTh, g_xTh); cudaGetSymbolAddress((void**)&xTl, g_xTl);
    cudaGetSymbolAddress((void**)&Gh,  g_Gh);  cudaGetSymbolAddress((void**)&Gl,  g_Gl);
    cudaGetSymbolAddress((void**)&PTh, g_PTh); cudaGetSymbolAddress((void**)&PTl, g_PTl);
    cudaGetSymbolAddress((void**)&RTh, g_RTh); cudaGetSymbolAddress((void**)&RTl, g_RTl);
    cudaGetSymbolAddress((void**)&Uh,  g_Uh);  cudaGetSymbolAddress((void**)&Ul,  g_Ul);
    cudaGetSymbolAddress((void**)&CTh, g_CTh); cudaGetSymbolAddress((void**)&CTl, g_CTl);
    cudaGetSymbolAddress((void**)&Wkbh,g_Wkbh);cudaGetSymbolAddress((void**)&Wkbl,g_Wkbl);
    cudaGetSymbolAddress((void**)&Wobh,g_Wobh);cudaGetSymbolAddress((void**)&Wobl,g_Wobl);
    cudaGetSymbolAddress((void**)&WvTh,g_WvTh);cudaGetSymbolAddress((void**)&WvTl,g_WvTl);
    cudaGetSymbolAddress((void**)&Wqbh,g_Wqbh);cudaGetSymbolAddress((void**)&Wqbl,g_Wqbl);
    cudaGetSymbolAddress((void**)&Gp,  g_Gp);  cudaGetSymbolAddress((void**)&Pp,  g_Pp);
    cudaGetSymbolAddress((void**)&Cp,  g_Cp);

    pack_all<<<12288, 256>>>(x, Wq, Wk, Wv, Wo);

    // G[n][m] = sum_l xT[n][l] xT[m][l]; split-K 4, fp32 partials
    gemm_bf3<128,128,0><<<dim3(4,4,8), 256, 131072>>>(
        xTh, xTl, xTh, xTl, Gp, nullptr, nullptr,
        1024, LSEQ, LSEQ, 512,
        (long)bX, 1024, (long)bX, 1024, (long)(4*bS), (long)bS, 4);
    reduce_ns<4><<<512, 256>>>(Gp, Gh, Gl);

    // PT[c][n] = sum_m Wkb[c][m] G[n][m]  (G symmetric); split-K 4
    gemm_bf3<128,128,0><<<dim3(4,4,8), 256, 131072>>>(
        Wkbh, Wkbl, Gh, Gl, Pp, nullptr, nullptr,
        128, 512, 512, 512,
        0, 128, (long)bS, 128, (long)(4*bS), (long)bS, 4);
    reduce_ns<4><<<512, 256>>>(Pp, PTh, PTl);

    // RT[v][k](b,h) = sum_n WvT[hv][n] PT[hk][n]; batched (b,h)
    gemm_bf3<64,64,1><<<dim3(1,1,16), 256, 65536>>>(
        WvTh, WvTl, PTh, PTl, nullptr, RTh, RTl,
        512, 512, 512, 64,
        0, 32768, (long)bS, 32768, (long)(NH*4096), 4096, NH);

    // U[j][hv](b) = sum_k Wqb[hj][k] RT[v][k]; batched (b,h)
    gemm_bf3<128,64,1><<<dim3(1,4,16), 256, 98304>>>(
        Wqbh, Wqbl, RTh, RTl, nullptr, Uh, Ul,
        64, 64, 64, 512,
        0, 32768, (long)(NH*4096), 4096, (long)bS, 64, NH);

    // CT[o][j](b) = sum_hv Wob[o][hv] U[j][hv]; split-K 4
    gemm_bf3<128,128,0><<<dim3(4,4,8), 256, 131072>>>(
        Wobh, Wobl, Uh, Ul, Cp, nullptr, nullptr,
        128, 512, 512, 512,
        0, 128, (long)bS, 128, (long)(4*bS), (long)bS, 4);
    reduce_ns<4><<<512, 256>>>(Cp, CTh, CTl);

    // out[l][o] = sum_j x[l][j] CT[o][j]
    gemm_bf3<128,128,0><<<dim3(4,32,2), 256, 131072>>>(
        xh, xl, CTh, CTl, out, nullptr, nullptr,
        512, 512, 512, 512,
        (long)bX, 0, (long)bS, 0, (long)bX, 0, 1);
}